// round 1
// baseline (speedup 1.0000x reference)
#include <cuda_runtime.h>

#define TSEQ 2048
#define BATCH 8
#define DM 1024
#define HD 128
#define MTOT (BATCH * TSEQ)

// Scratch for projected Q/K/V: [B*T, 128] each (8 MB each)
__device__ __align__(16) float g_q[MTOT * HD];
__device__ __align__(16) float g_k[MTOT * HD];
__device__ __align__(16) float g_v[MTOT * HD];

// ---------------------------------------------------------------------------
// Kernel 1: QKV projection. y[m,h] = sum_c x[m,c] * W[h,c]
// BM=128, BN=128 (full head_dim), BK=32. 256 threads, 8x8 per thread.
// blockIdx.y selects (Wq, Wk, Wv) -> (g_q, g_k, g_v).
// ---------------------------------------------------------------------------
__global__ __launch_bounds__(256) void qkv_kernel(
    const float* __restrict__ x, const float* __restrict__ Wq,
    const float* __restrict__ Wk, const float* __restrict__ Wv) {
  __shared__ float Xt[32][129];  // [k][m], pad 129 -> conflict-free transposed stores
  __shared__ float Wt[32][129];  // [k][n]

  const float* W = (blockIdx.y == 0) ? Wq : (blockIdx.y == 1 ? Wk : Wv);
  float* outp = (blockIdx.y == 0) ? g_q : (blockIdx.y == 1 ? g_k : g_v);

  const int tid = threadIdx.x;
  const int tx = tid & 15, ty = tid >> 4;
  const int m0 = blockIdx.x * 128;

  float acc[8][8];
#pragma unroll
  for (int i = 0; i < 8; i++)
#pragma unroll
    for (int j = 0; j < 8; j++) acc[i][j] = 0.f;

  for (int k0 = 0; k0 < DM; k0 += 32) {
#pragma unroll
    for (int it = 0; it < 4; it++) {
      int idx = tid + it * 256;      // 1024 float4 per tile
      int r = idx >> 3, c4 = idx & 7;
      float4 xv = *(const float4*)&x[(size_t)(m0 + r) * DM + k0 + c4 * 4];
      Xt[c4 * 4 + 0][r] = xv.x; Xt[c4 * 4 + 1][r] = xv.y;
      Xt[c4 * 4 + 2][r] = xv.z; Xt[c4 * 4 + 3][r] = xv.w;
      float4 wv = *(const float4*)&W[(size_t)r * DM + k0 + c4 * 4];
      Wt[c4 * 4 + 0][r] = wv.x; Wt[c4 * 4 + 1][r] = wv.y;
      Wt[c4 * 4 + 2][r] = wv.z; Wt[c4 * 4 + 3][r] = wv.w;
    }
    __syncthreads();
#pragma unroll
    for (int k = 0; k < 32; k++) {
      float a[8], bb[8];
#pragma unroll
      for (int i = 0; i < 8; i++) a[i] = Xt[k][ty * 8 + i];
#pragma unroll
      for (int j = 0; j < 8; j++) bb[j] = Wt[k][tx * 8 + j];
#pragma unroll
      for (int i = 0; i < 8; i++)
#pragma unroll
        for (int j = 0; j < 8; j++) acc[i][j] += a[i] * bb[j];
    }
    __syncthreads();
  }

#pragma unroll
  for (int i = 0; i < 8; i++) {
    int m = m0 + ty * 8 + i;
#pragma unroll
    for (int j4 = 0; j4 < 2; j4++) {
      float4 v = make_float4(acc[i][j4 * 4 + 0], acc[i][j4 * 4 + 1],
                             acc[i][j4 * 4 + 2], acc[i][j4 * 4 + 3]);
      *(float4*)&outp[(size_t)m * HD + tx * 8 + j4 * 4] = v;
    }
  }
}

// ---------------------------------------------------------------------------
// Kernel 2: causal flash attention. BQ=64, BKV=64, 256 threads (16x16).
// Thread (tx,ty): S tile rows 4ty..+4 x cols 4tx..+4; O tile rows 4ty..+4 x
// cols 8tx..+8. K stored d-major with XOR swizzle -> conflict-free f4 reads.
// ---------------------------------------------------------------------------
__global__ __launch_bounds__(256) void attn_kernel(float* __restrict__ out) {
  extern __shared__ float sm[];
  float* Qs = sm;                  // [64][128]   contiguous
  float* Kt = sm + 64 * 128;       // swizzled [128 d][64 n]
  float* Vs = Kt + 128 * 64;       // [64][132]   (pad 4)
  float* Ps = Vs + 64 * 132;       // [64][68]    (pad 4)
  float4* Qs4 = (float4*)Qs;
  float4* Kt4 = (float4*)Kt;
  float4* Vs4 = (float4*)Vs;

  const int tid = threadIdx.x;
  const int tx = tid & 15, ty = tid >> 4;
  const int qb = blockIdx.x, b = blockIdx.y;
  const size_t qbase = ((size_t)b * TSEQ + (size_t)qb * 64) * HD;

  {
    const float4* src = (const float4*)(g_q + qbase);
#pragma unroll
    for (int it = 0; it < 8; it++) {
      int idx = tid + it * 256;
      Qs4[idx] = src[idx];
    }
  }

  float O[4][8];
  float m_r[4], l_r[4];
#pragma unroll
  for (int i = 0; i < 4; i++) {
    m_r[i] = -1e30f; l_r[i] = 0.f;
#pragma unroll
    for (int j = 0; j < 8; j++) O[i][j] = 0.f;
  }
  const float sscale = 0.08838834764831845f;  // 1/sqrt(128)

  for (int kb = 0; kb <= qb; kb++) {
    __syncthreads();  // prev-iter Ps/Vs consumers done before overwrite
    const size_t kbase = ((size_t)b * TSEQ + (size_t)kb * 64) * HD;
    const float4* ksrc = (const float4*)(g_k + kbase);
    const float4* vsrc = (const float4*)(g_v + kbase);
#pragma unroll
    for (int it = 0; it < 8; it++) {
      int idx = tid + it * 256;
      int n = idx >> 5, d4l = idx & 31;  // per-warp: n fixed, d4l = lane
      float4 kvv = ksrc[idx];
      int n4 = n >> 2, nl = n & 3;
      int xo = n4 ^ (d4l & 15);          // swizzle: f4idx = 16*d + (n4 ^ (d>>2 & 15))
      Kt[((4 * d4l + 0) * 16 + xo) * 4 + nl] = kvv.x;
      Kt[((4 * d4l + 1) * 16 + xo) * 4 + nl] = kvv.y;
      Kt[((4 * d4l + 2) * 16 + xo) * 4 + nl] = kvv.z;
      Kt[((4 * d4l + 3) * 16 + xo) * 4 + nl] = kvv.w;
      Vs4[n * 33 + d4l] = vsrc[idx];
    }
    __syncthreads();

    // S = Q K^T
    float4 s4[4];
#pragma unroll
    for (int i = 0; i < 4; i++) s4[i] = make_float4(0.f, 0.f, 0.f, 0.f);
#pragma unroll 4
    for (int d4 = 0; d4 < 32; d4++) {
      int xo = tx ^ (d4 & 15);
      float4 kk0 = Kt4[(4 * d4 + 0) * 16 + xo];
      float4 kk1 = Kt4[(4 * d4 + 1) * 16 + xo];
      float4 kk2 = Kt4[(4 * d4 + 2) * 16 + xo];
      float4 kk3 = Kt4[(4 * d4 + 3) * 16 + xo];
#pragma unroll
      for (int i = 0; i < 4; i++) {
        float4 q4 = Qs4[(4 * ty + i) * 32 + d4];
        s4[i].x += q4.x * kk0.x + q4.y * kk1.x + q4.z * kk2.x + q4.w * kk3.x;
        s4[i].y += q4.x * kk0.y + q4.y * kk1.y + q4.z * kk2.y + q4.w * kk3.y;
        s4[i].z += q4.x * kk0.z + q4.y * kk1.z + q4.z * kk2.z + q4.w * kk3.z;
        s4[i].w += q4.x * kk0.w + q4.y * kk1.w + q4.z * kk2.w + q4.w * kk3.w;
      }
    }

    // online softmax
#pragma unroll
    for (int i = 0; i < 4; i++) {
      float sx = s4[i].x * sscale, sy = s4[i].y * sscale;
      float sz = s4[i].z * sscale, sw = s4[i].w * sscale;
      int qrow = qb * 64 + 4 * ty + i;
      if (kb == qb) {
        int kc = kb * 64 + 4 * tx;
        if (kc + 0 > qrow) sx = -1e30f;
        if (kc + 1 > qrow) sy = -1e30f;
        if (kc + 2 > qrow) sz = -1e30f;
        if (kc + 3 > qrow) sw = -1e30f;
      }
      float mx = fmaxf(fmaxf(sx, sy), fmaxf(sz, sw));
#pragma unroll
      for (int o = 8; o; o >>= 1)
        mx = fmaxf(mx, __shfl_xor_sync(0xffffffffu, mx, o));
      float newm = fmaxf(m_r[i], mx);
      float corr = __expf(m_r[i] - newm);
      m_r[i] = newm;
      float px = __expf(sx - newm), py = __expf(sy - newm);
      float pz = __expf(sz - newm), pw = __expf(sw - newm);
      l_r[i] = l_r[i] * corr + (px + py + pz + pw);
#pragma unroll
      for (int j = 0; j < 8; j++) O[i][j] *= corr;
      ((float4*)Ps)[(4 * ty + i) * 17 + tx] = make_float4(px, py, pz, pw);
    }
    __syncthreads();

    // O += P @ V
#pragma unroll 8
    for (int k = 0; k < 64; k++) {
      float4 v0 = Vs4[k * 33 + 2 * tx];
      float4 v1 = Vs4[k * 33 + 2 * tx + 1];
#pragma unroll
      for (int i = 0; i < 4; i++) {
        float pp = Ps[(4 * ty + i) * 68 + k];
        O[i][0] += pp * v0.x; O[i][1] += pp * v0.y;
        O[i][2] += pp * v0.z; O[i][3] += pp * v0.w;
        O[i][4] += pp * v1.x; O[i][5] += pp * v1.y;
        O[i][6] += pp * v1.z; O[i][7] += pp * v1.w;
      }
    }
  }

  // epilogue: normalize and write
#pragma unroll
  for (int i = 0; i < 4; i++) {
    float ls = l_r[i];
#pragma unroll
    for (int o = 8; o; o >>= 1) ls += __shfl_xor_sync(0xffffffffu, ls, o);
    float inv = 1.f / ls;
    int t = qb * 64 + 4 * ty + i;
    float* op = out + ((size_t)b * TSEQ + t) * HD + tx * 8;
    *(float4*)op = make_float4(O[i][0] * inv, O[i][1] * inv,
                               O[i][2] * inv, O[i][3] * inv);
    *(float4*)(op + 4) = make_float4(O[i][4] * inv, O[i][5] * inv,
                                     O[i][6] * inv, O[i][7] * inv);
  }
}

extern "C" void kernel_launch(void* const* d_in, const int* in_sizes, int n_in,
                              void* d_out, int out_size) {
  (void)in_sizes; (void)n_in; (void)out_size;
  const float* x  = (const float*)d_in[0];
  const float* Wq = (const float*)d_in[1];
  const float* Wk = (const float*)d_in[2];
  const float* Wv = (const float*)d_in[3];
  float* out = (float*)d_out;

  dim3 g1(128, 3);
  qkv_kernel<<<g1, 256>>>(x, Wq, Wk, Wv);

  const int SMEM = (64 * 128 + 128 * 64 + 64 * 132 + 64 * 68) * 4;  // 116736 B
  cudaFuncSetAttribute(attn_kernel, cudaFuncAttributeMaxDynamicSharedMemorySize,
                       SMEM);
  dim3 g2(32, 8);
  attn_kernel<<<g2, 256, SMEM>>>(out);
}

// round 2
// speedup vs baseline: 1.0398x; 1.0398x over previous
#include <cuda_runtime.h>

#define TSEQ 2048
#define BATCH 8
#define DM 1024
#define HD 128
#define MTOT (BATCH * TSEQ)

// Scratch for projected Q/K/V: [B*T, 128] each (8 MB each). Q is pre-scaled by 1/sqrt(HD).
__device__ __align__(16) float g_q[MTOT * HD];
__device__ __align__(16) float g_k[MTOT * HD];
__device__ __align__(16) float g_v[MTOT * HD];

// ---------------------------------------------------------------------------
// tf32 helpers
// ---------------------------------------------------------------------------
__device__ __forceinline__ float f2tf32(float f) {
  unsigned r;
  asm("cvt.rna.tf32.f32 %0, %1;" : "=r"(r) : "f"(f));
  return __uint_as_float(r);
}

__device__ __forceinline__ void mma_tf32(float* d, const unsigned* a,
                                         const unsigned* b) {
  asm volatile(
      "mma.sync.aligned.m16n8k8.row.col.f32.tf32.tf32.f32 "
      "{%0,%1,%2,%3}, {%4,%5,%6,%7}, {%8,%9}, {%0,%1,%2,%3};\n"
      : "+f"(d[0]), "+f"(d[1]), "+f"(d[2]), "+f"(d[3])
      : "r"(a[0]), "r"(a[1]), "r"(a[2]), "r"(a[3]), "r"(b[0]), "r"(b[1]));
}

// ---------------------------------------------------------------------------
// Kernel 1: QKV projection with tf32 tensor cores + hi/lo split (fp32 accuracy)
// y[m,h] = sum_c x[m,c] * W[h,c].  BM=128, BN=128, BK=32. 256 thr = 8 warps,
// warp grid 2(m) x 4(n); warp tile 64x32 = 4x4 mma m16n8k8 tiles.
// acc += Ahi*Bhi + Ahi*Blo + Alo*Bhi  (error ~2^-22).
// ---------------------------------------------------------------------------
#define QK_STRIDE 44  // pad 32->44: frag-load banks (12g+tig)%32 all distinct; 44*4 % 16 == 0

__global__ __launch_bounds__(256, 2) void qkv_kernel(
    const float* __restrict__ x, const float* __restrict__ Wq,
    const float* __restrict__ Wk, const float* __restrict__ Wv) {
  extern __shared__ float qsm[];
  float* Ah = qsm;                    // [128][44]
  float* Al = qsm + 128 * QK_STRIDE;  // [128][44]
  float* Bh = Al + 128 * QK_STRIDE;
  float* Bl = Bh + 128 * QK_STRIDE;

  const float* W = (blockIdx.y == 0) ? Wq : (blockIdx.y == 1 ? Wk : Wv);
  float* outp = (blockIdx.y == 0) ? g_q : (blockIdx.y == 1 ? g_k : g_v);

  const int tid = threadIdx.x;
  const int lane = tid & 31, wid = tid >> 5;
  const int wm = wid >> 2, wn = wid & 3;  // 2 x 4 warp grid
  const int g = lane >> 2, tig = lane & 3;
  const int m0 = blockIdx.x * 128;

  float acc[4][4][4];
#pragma unroll
  for (int i = 0; i < 4; i++)
#pragma unroll
    for (int j = 0; j < 4; j++)
#pragma unroll
      for (int r = 0; r < 4; r++) acc[i][j][r] = 0.f;

  for (int k0 = 0; k0 < DM; k0 += 32) {
#pragma unroll
    for (int it = 0; it < 4; it++) {
      int idx = tid + it * 256;  // 1024 float4 per matrix tile
      int r = idx >> 3, c4 = idx & 7;
      float4 xv = *(const float4*)&x[(size_t)(m0 + r) * DM + k0 + c4 * 4];
      float hx = f2tf32(xv.x), hy = f2tf32(xv.y);
      float hz = f2tf32(xv.z), hw = f2tf32(xv.w);
      *(float4*)&Ah[r * QK_STRIDE + c4 * 4] = make_float4(hx, hy, hz, hw);
      *(float4*)&Al[r * QK_STRIDE + c4 * 4] =
          make_float4(xv.x - hx, xv.y - hy, xv.z - hz, xv.w - hw);
      float4 wv = *(const float4*)&W[(size_t)r * DM + k0 + c4 * 4];
      float gx = f2tf32(wv.x), gy = f2tf32(wv.y);
      float gz = f2tf32(wv.z), gw = f2tf32(wv.w);
      *(float4*)&Bh[r * QK_STRIDE + c4 * 4] = make_float4(gx, gy, gz, gw);
      *(float4*)&Bl[r * QK_STRIDE + c4 * 4] =
          make_float4(wv.x - gx, wv.y - gy, wv.z - gz, wv.w - gw);
    }
    __syncthreads();

#pragma unroll
    for (int ks = 0; ks < 4; ks++) {
      const int kk = ks * 8;
      unsigned bh[4][2], bl[4][2];
#pragma unroll
      for (int j = 0; j < 4; j++) {
        int n = wn * 32 + j * 8 + g;
        bh[j][0] = __float_as_uint(Bh[n * QK_STRIDE + kk + tig]);
        bh[j][1] = __float_as_uint(Bh[n * QK_STRIDE + kk + tig + 4]);
        bl[j][0] = __float_as_uint(Bl[n * QK_STRIDE + kk + tig]);
        bl[j][1] = __float_as_uint(Bl[n * QK_STRIDE + kk + tig + 4]);
      }
#pragma unroll
      for (int i = 0; i < 4; i++) {
        int m = wm * 64 + i * 16 + g;
        unsigned ah[4], al[4];
        ah[0] = __float_as_uint(Ah[m * QK_STRIDE + kk + tig]);
        ah[1] = __float_as_uint(Ah[(m + 8) * QK_STRIDE + kk + tig]);
        ah[2] = __float_as_uint(Ah[m * QK_STRIDE + kk + tig + 4]);
        ah[3] = __float_as_uint(Ah[(m + 8) * QK_STRIDE + kk + tig + 4]);
        al[0] = __float_as_uint(Al[m * QK_STRIDE + kk + tig]);
        al[1] = __float_as_uint(Al[(m + 8) * QK_STRIDE + kk + tig]);
        al[2] = __float_as_uint(Al[m * QK_STRIDE + kk + tig + 4]);
        al[3] = __float_as_uint(Al[(m + 8) * QK_STRIDE + kk + tig + 4]);
#pragma unroll
        for (int j = 0; j < 4; j++) {
          mma_tf32(acc[i][j], ah, bh[j]);
          mma_tf32(acc[i][j], ah, bl[j]);
          mma_tf32(acc[i][j], al, bh[j]);
        }
      }
    }
    __syncthreads();
  }

  const float qs = (blockIdx.y == 0) ? 0.08838834764831845f : 1.0f;
#pragma unroll
  for (int i = 0; i < 4; i++) {
    int rbase = m0 + wm * 64 + i * 16 + g;
#pragma unroll
    for (int j = 0; j < 4; j++) {
      int col = wn * 32 + j * 8 + tig * 2;
      *(float2*)&outp[(size_t)rbase * HD + col] =
          make_float2(acc[i][j][0] * qs, acc[i][j][1] * qs);
      *(float2*)&outp[(size_t)(rbase + 8) * HD + col] =
          make_float2(acc[i][j][2] * qs, acc[i][j][3] * qs);
    }
  }
}

// ---------------------------------------------------------------------------
// Kernel 2: causal flash attention. BQ=BKV=64, 256 threads (16x16), 2 CTA/SM.
// Q swizzled (bank-conflict-free), K d-major XOR swizzle, V unpadded with
// contiguous-column reads. Q pre-scaled by 1/sqrt(HD).
// ---------------------------------------------------------------------------
__global__ __launch_bounds__(256, 2) void attn_kernel(float* __restrict__ out) {
  extern __shared__ float sm[];
  float* Qs = sm;                  // [64][128] f4-swizzled: idx = r*32 + (d4 ^ ((r>>2 & 1)*4))
  float* Kt = sm + 64 * 128;       // swizzled [128 d][64 n]
  float* Vs = Kt + 128 * 64;       // [64][128] no pad
  float* Ps = Vs + 64 * 128;       // [64][66]
  float4* Qs4 = (float4*)Qs;
  float4* Kt4 = (float4*)Kt;
  float4* Vs4 = (float4*)Vs;
  float2* Ps2 = (float2*)Ps;

  const int tid = threadIdx.x;
  const int tx = tid & 15, ty = tid >> 4;
  const int qb = blockIdx.x, b = blockIdx.y;
  const size_t qbase = ((size_t)b * TSEQ + (size_t)qb * 64) * HD;

  {
    const float4* src = (const float4*)(g_q + qbase);
#pragma unroll
    for (int it = 0; it < 8; it++) {
      int idx = tid + it * 256;
      int row = idx >> 5, d4 = idx & 31;
      Qs4[row * 32 + (d4 ^ (((row >> 2) & 1) * 4))] = src[idx];
    }
  }

  float O[4][8];  // cols: [0..3] -> 4tx..4tx+3, [4..7] -> 64+4tx..64+4tx+3
  float m_r[4], l_r[4];
#pragma unroll
  for (int i = 0; i < 4; i++) {
    m_r[i] = -1e30f; l_r[i] = 0.f;
#pragma unroll
    for (int j = 0; j < 8; j++) O[i][j] = 0.f;
  }
  const int swzq = (ty & 1) * 4;  // rows 4ty..4ty+3 share (row>>2)&1 == ty&1

  for (int kb = 0; kb <= qb; kb++) {
    __syncthreads();
    const size_t kbase = ((size_t)b * TSEQ + (size_t)kb * 64) * HD;
    const float4* ksrc = (const float4*)(g_k + kbase);
    const float4* vsrc = (const float4*)(g_v + kbase);
#pragma unroll
    for (int it = 0; it < 8; it++) {
      int idx = tid + it * 256;
      int n = idx >> 5, d4l = idx & 31;
      float4 kvv = ksrc[idx];
      int n4 = n >> 2, nl = n & 3;
      int xo = n4 ^ (d4l & 15);
      Kt[((4 * d4l + 0) * 16 + xo) * 4 + nl] = kvv.x;
      Kt[((4 * d4l + 1) * 16 + xo) * 4 + nl] = kvv.y;
      Kt[((4 * d4l + 2) * 16 + xo) * 4 + nl] = kvv.z;
      Kt[((4 * d4l + 3) * 16 + xo) * 4 + nl] = kvv.w;
      Vs4[n * 32 + d4l] = vsrc[idx];
    }
    __syncthreads();

    // S = Q K^T
    float4 s4[4];
#pragma unroll
    for (int i = 0; i < 4; i++) s4[i] = make_float4(0.f, 0.f, 0.f, 0.f);
#pragma unroll 4
    for (int d4 = 0; d4 < 32; d4++) {
      int xo = tx ^ (d4 & 15);
      float4 kk0 = Kt4[(4 * d4 + 0) * 16 + xo];
      float4 kk1 = Kt4[(4 * d4 + 1) * 16 + xo];
      float4 kk2 = Kt4[(4 * d4 + 2) * 16 + xo];
      float4 kk3 = Kt4[(4 * d4 + 3) * 16 + xo];
      int qd4 = d4 ^ swzq;
#pragma unroll
      for (int i = 0; i < 4; i++) {
        float4 q4 = Qs4[(4 * ty + i) * 32 + qd4];
        s4[i].x += q4.x * kk0.x + q4.y * kk1.x + q4.z * kk2.x + q4.w * kk3.x;
        s4[i].y += q4.x * kk0.y + q4.y * kk1.y + q4.z * kk2.y + q4.w * kk3.y;
        s4[i].z += q4.x * kk0.z + q4.y * kk1.z + q4.z * kk2.z + q4.w * kk3.z;
        s4[i].w += q4.x * kk0.w + q4.y * kk1.w + q4.z * kk2.w + q4.w * kk3.w;
      }
    }

    // online softmax (Q pre-scaled, no sscale here)
#pragma unroll
    for (int i = 0; i < 4; i++) {
      float sx = s4[i].x, sy = s4[i].y, sz = s4[i].z, sw = s4[i].w;
      int qrow = qb * 64 + 4 * ty + i;
      if (kb == qb) {
        int kc = kb * 64 + 4 * tx;
        if (kc + 0 > qrow) sx = -1e30f;
        if (kc + 1 > qrow) sy = -1e30f;
        if (kc + 2 > qrow) sz = -1e30f;
        if (kc + 3 > qrow) sw = -1e30f;
      }
      float mx = fmaxf(fmaxf(sx, sy), fmaxf(sz, sw));
#pragma unroll
      for (int o = 8; o; o >>= 1)
        mx = fmaxf(mx, __shfl_xor_sync(0xffffffffu, mx, o));
      float newm = fmaxf(m_r[i], mx);
      float corr = __expf(m_r[i] - newm);
      m_r[i] = newm;
      float px = __expf(sx - newm), py = __expf(sy - newm);
      float pz = __expf(sz - newm), pw = __expf(sw - newm);
      l_r[i] = l_r[i] * corr + (px + py + pz + pw);
#pragma unroll
      for (int j = 0; j < 8; j++) O[i][j] *= corr;
      Ps2[(4 * ty + i) * 33 + 2 * tx] = make_float2(px, py);
      Ps2[(4 * ty + i) * 33 + 2 * tx + 1] = make_float2(pz, pw);
    }
    __syncthreads();

    // O += P @ V   (contiguous V columns: tx and 16+tx)
#pragma unroll 8
    for (int k = 0; k < 64; k++) {
      float4 v0 = Vs4[k * 32 + tx];
      float4 v1 = Vs4[k * 32 + 16 + tx];
#pragma unroll
      for (int i = 0; i < 4; i++) {
        float pp = Ps[(4 * ty + i) * 66 + k];
        O[i][0] += pp * v0.x; O[i][1] += pp * v0.y;
        O[i][2] += pp * v0.z; O[i][3] += pp * v0.w;
        O[i][4] += pp * v1.x; O[i][5] += pp * v1.y;
        O[i][6] += pp * v1.z; O[i][7] += pp * v1.w;
      }
    }
  }

  // epilogue: normalize and write
#pragma unroll
  for (int i = 0; i < 4; i++) {
    float ls = l_r[i];
#pragma unroll
    for (int o = 8; o; o >>= 1) ls += __shfl_xor_sync(0xffffffffu, ls, o);
    float inv = 1.f / ls;
    int t = qb * 64 + 4 * ty + i;
    float* op = out + ((size_t)b * TSEQ + t) * HD;
    *(float4*)(op + tx * 4) = make_float4(O[i][0] * inv, O[i][1] * inv,
                                          O[i][2] * inv, O[i][3] * inv);
    *(float4*)(op + 64 + tx * 4) = make_float4(O[i][4] * inv, O[i][5] * inv,
                                               O[i][6] * inv, O[i][7] * inv);
  }
}

extern "C" void kernel_launch(void* const* d_in, const int* in_sizes, int n_in,
                              void* d_out, int out_size) {
  (void)in_sizes; (void)n_in; (void)out_size;
  const float* x  = (const float*)d_in[0];
  const float* Wq = (const float*)d_in[1];
  const float* Wk = (const float*)d_in[2];
  const float* Wv = (const float*)d_in[3];
  float* out = (float*)d_out;

  const int SMEMQ = 4 * 128 * QK_STRIDE * 4;  // 90112 B
  cudaFuncSetAttribute(qkv_kernel, cudaFuncAttributeMaxDynamicSharedMemorySize,
                       SMEMQ);
  dim3 g1(128, 3);
  qkv_kernel<<<g1, 256, SMEMQ>>>(x, Wq, Wk, Wv);

  const int SMEM = (64 * 128 + 128 * 64 + 64 * 128 + 64 * 66) * 4;  // 115200 B
  cudaFuncSetAttribute(attn_kernel, cudaFuncAttributeMaxDynamicSharedMemorySize,
                       SMEM);
  dim3 g2(32, 8);
  attn_kernel<<<g2, 256, SMEM>>>(out);
}

// round 4
// speedup vs baseline: 1.3057x; 1.2557x over previous
#include <cuda_runtime.h>
#include <cuda_bf16.h>
#include <cstdint>

#define TSEQ 2048
#define BATCH 8
#define DM 1024
#define HD 128
#define MTOT (BATCH * TSEQ)

// Scratch for projected Q/K/V: [B*T, 128] each. Q pre-scaled by 1/sqrt(HD).
__device__ __align__(16) float g_q[MTOT * HD];
__device__ __align__(16) float g_k[MTOT * HD];
__device__ __align__(16) float g_v[MTOT * HD];

__device__ __forceinline__ uint32_t smem_u32(const void* p) {
  return (uint32_t)__cvta_generic_to_shared(p);
}

__device__ __forceinline__ void mma_bf16(float* d, const uint32_t* a,
                                         const uint32_t* b) {
  asm volatile(
      "mma.sync.aligned.m16n8k16.row.col.f32.bf16.bf16.f32 "
      "{%0,%1,%2,%3}, {%4,%5,%6,%7}, {%8,%9}, {%0,%1,%2,%3};\n"
      : "+f"(d[0]), "+f"(d[1]), "+f"(d[2]), "+f"(d[3])
      : "r"(a[0]), "r"(a[1]), "r"(a[2]), "r"(a[3]), "r"(b[0]), "r"(b[1]));
}

__device__ __forceinline__ void ldm_x4(uint32_t* r, uint32_t addr) {
  asm volatile(
      "ldmatrix.sync.aligned.m8n8.x4.shared.b16 {%0,%1,%2,%3}, [%4];"
      : "=r"(r[0]), "=r"(r[1]), "=r"(r[2]), "=r"(r[3]) : "r"(addr));
}

// Convert 8 fp32 -> 8 bf16 hi + 8 bf16 lo (packed 16B each)
__device__ __forceinline__ void cvt8(float4 a0, float4 a1, uint4& hi, uint4& lo) {
  __nv_bfloat162 h0 = __floats2bfloat162_rn(a0.x, a0.y);
  __nv_bfloat162 h1 = __floats2bfloat162_rn(a0.z, a0.w);
  __nv_bfloat162 h2 = __floats2bfloat162_rn(a1.x, a1.y);
  __nv_bfloat162 h3 = __floats2bfloat162_rn(a1.z, a1.w);
  __nv_bfloat162 l0 = __floats2bfloat162_rn(a0.x - __bfloat162float(h0.x),
                                            a0.y - __bfloat162float(h0.y));
  __nv_bfloat162 l1 = __floats2bfloat162_rn(a0.z - __bfloat162float(h1.x),
                                            a0.w - __bfloat162float(h1.y));
  __nv_bfloat162 l2 = __floats2bfloat162_rn(a1.x - __bfloat162float(h2.x),
                                            a1.y - __bfloat162float(h2.y));
  __nv_bfloat162 l3 = __floats2bfloat162_rn(a1.z - __bfloat162float(h3.x),
                                            a1.w - __bfloat162float(h3.y));
  hi = make_uint4(*(uint32_t*)&h0, *(uint32_t*)&h1, *(uint32_t*)&h2, *(uint32_t*)&h3);
  lo = make_uint4(*(uint32_t*)&l0, *(uint32_t*)&l1, *(uint32_t*)&l2, *(uint32_t*)&l3);
}

// ---------------------------------------------------------------------------
// Kernel 1: QKV projection. D[128,128] = X[128,1024] * W[128,1024]^T per CTA.
// bf16 m16n8k16 mma + ldmatrix, hi/lo split-3. BK=32, double-buffered smem,
// 80B row stride (ldmatrix conflict-free). 512 threads, warp grid 4x4,
// warp tile 32x32.
// ---------------------------------------------------------------------------
#define RSTRIDE 80
#define TILE_B (128 * RSTRIDE)  // 10240
#define BUF_B (4 * TILE_B)      // 40960: Ah, Al, Bh, Bl

__global__ __launch_bounds__(512) void qkv_hmma(
    const float* __restrict__ x, const float* __restrict__ Wq,
    const float* __restrict__ Wk, const float* __restrict__ Wv) {
  extern __shared__ __align__(1024) char smem[];
  const float* W = (blockIdx.y == 0) ? Wq : (blockIdx.y == 1 ? Wk : Wv);
  float* outp = (blockIdx.y == 0) ? g_q : (blockIdx.y == 1 ? g_k : g_v);

  const int tid = threadIdx.x;
  const int lane = tid & 31, wid = tid >> 5;
  const int wm = wid >> 2, wn = wid & 3;
  const int m0 = blockIdx.x * 128;
  const uint32_t sb = smem_u32(smem);

  // loader role: row 0..127, 16B k-chunk c 0..3
  const int lrow = tid >> 2, lc = tid & 3;
  const float* aSrc = x + (size_t)(m0 + lrow) * DM + lc * 8;
  const float* bSrc = W + (size_t)lrow * DM + lc * 8;
  const uint32_t stoOff = lrow * RSTRIDE + lc * 16;

  // fragment address components
  const int lane15 = lane & 15;
  const uint32_t aColOff = (lane >> 4) * 16;
  const uint32_t aRowB = (wm * 32 + lane15) * RSTRIDE;
  const uint32_t bRowB = (wn * 32 + ((lane >> 4) << 3) + (lane & 7)) * RSTRIDE;
  const uint32_t bColOff = ((lane >> 3) & 1) * 16;

  float acc[2][4][4];
#pragma unroll
  for (int i = 0; i < 2; i++)
#pragma unroll
    for (int j = 0; j < 4; j++)
#pragma unroll
      for (int r = 0; r < 4; r++) acc[i][j][r] = 0.f;

  float4 pA0, pA1, pB0, pB1;
  // prologue: chunk 0
  pA0 = *(const float4*)(aSrc);
  pA1 = *(const float4*)(aSrc + 4);
  pB0 = *(const float4*)(bSrc);
  pB1 = *(const float4*)(bSrc + 4);
  {
    uint4 hi, lo;
    char* p = smem + stoOff;
    cvt8(pA0, pA1, hi, lo);
    *(uint4*)(p) = hi;
    *(uint4*)(p + TILE_B) = lo;
    cvt8(pB0, pB1, hi, lo);
    *(uint4*)(p + 2 * TILE_B) = hi;
    *(uint4*)(p + 3 * TILE_B) = lo;
  }
  __syncthreads();

  for (int kt = 0; kt < 32; kt++) {
    if (kt < 31) {
      const float* a = aSrc + (kt + 1) * 32;
      const float* b = bSrc + (kt + 1) * 32;
      pA0 = *(const float4*)(a);
      pA1 = *(const float4*)(a + 4);
      pB0 = *(const float4*)(b);
      pB1 = *(const float4*)(b + 4);
    }
    const uint32_t bufBase = sb + (kt & 1) * BUF_B;
#pragma unroll
    for (int s = 0; s < 2; s++) {
      uint32_t ah[2][4], al[2][4], bh[2][4], bl[2][4];
#pragma unroll
      for (int i = 0; i < 2; i++) {
        uint32_t aa = bufBase + aRowB + i * (16 * RSTRIDE) + s * 32 + aColOff;
        ldm_x4(ah[i], aa);
        ldm_x4(al[i], aa + TILE_B);
      }
#pragma unroll
      for (int j = 0; j < 2; j++) {
        uint32_t ba = bufBase + 2 * TILE_B + bRowB + j * (16 * RSTRIDE) + s * 32 + bColOff;
        ldm_x4(bh[j], ba);
        ldm_x4(bl[j], ba + TILE_B);
      }
#pragma unroll
      for (int i = 0; i < 2; i++)
#pragma unroll
        for (int jj = 0; jj < 4; jj++) {
          const uint32_t* bhp = &bh[jj >> 1][(jj & 1) * 2];
          const uint32_t* blp = &bl[jj >> 1][(jj & 1) * 2];
          mma_bf16(acc[i][jj], ah[i], bhp);
          mma_bf16(acc[i][jj], ah[i], blp);
          mma_bf16(acc[i][jj], al[i], bhp);
        }
    }
    if (kt < 31) {
      char* p = smem + ((kt + 1) & 1) * BUF_B + stoOff;
      uint4 hi, lo;
      cvt8(pA0, pA1, hi, lo);
      *(uint4*)(p) = hi;
      *(uint4*)(p + TILE_B) = lo;
      cvt8(pB0, pB1, hi, lo);
      *(uint4*)(p + 2 * TILE_B) = hi;
      *(uint4*)(p + 3 * TILE_B) = lo;
    }
    __syncthreads();
  }

  // epilogue
  const float qs = (blockIdx.y == 0) ? 0.08838834764831845f : 1.0f;
  const int g = lane >> 2, tig = lane & 3;
#pragma unroll
  for (int i = 0; i < 2; i++) {
    int r0 = m0 + wm * 32 + i * 16 + g;
#pragma unroll
    for (int jj = 0; jj < 4; jj++) {
      int col = wn * 32 + jj * 8 + 2 * tig;
      *(float2*)&outp[(size_t)r0 * HD + col] =
          make_float2(acc[i][jj][0] * qs, acc[i][jj][1] * qs);
      *(float2*)&outp[(size_t)(r0 + 8) * HD + col] =
          make_float2(acc[i][jj][2] * qs, acc[i][jj][3] * qs);
    }
  }
}

// ---------------------------------------------------------------------------
// Kernel 2: causal flash attention (unchanged, known-good 433us). 256 thr.
// ---------------------------------------------------------------------------
__global__ __launch_bounds__(256, 2) void attn_kernel(float* __restrict__ out) {
  extern __shared__ float sm[];
  float* Qs = sm;
  float* Kt = sm + 64 * 128;
  float* Vs = Kt + 128 * 64;
  float* Ps = Vs + 64 * 128;
  float4* Qs4 = (float4*)Qs;
  float4* Kt4 = (float4*)Kt;
  float4* Vs4 = (float4*)Vs;
  float2* Ps2 = (float2*)Ps;

  const int tid = threadIdx.x;
  const int tx = tid & 15, ty = tid >> 4;
  const int qb = blockIdx.x, b = blockIdx.y;
  const size_t qbase = ((size_t)b * TSEQ + (size_t)qb * 64) * HD;

  {
    const float4* src = (const float4*)(g_q + qbase);
#pragma unroll
    for (int it = 0; it < 8; it++) {
      int idx = tid + it * 256;
      int row = idx >> 5, d4 = idx & 31;
      Qs4[row * 32 + (d4 ^ (((row >> 2) & 1) * 4))] = src[idx];
    }
  }

  float O[4][8];
  float m_r[4], l_r[4];
#pragma unroll
  for (int i = 0; i < 4; i++) {
    m_r[i] = -1e30f; l_r[i] = 0.f;
#pragma unroll
    for (int j = 0; j < 8; j++) O[i][j] = 0.f;
  }
  const int swzq = (ty & 1) * 4;

  for (int kb = 0; kb <= qb; kb++) {
    __syncthreads();
    const size_t kbase = ((size_t)b * TSEQ + (size_t)kb * 64) * HD;
    const float4* ksrc = (const float4*)(g_k + kbase);
    const float4* vsrc = (const float4*)(g_v + kbase);
#pragma unroll
    for (int it = 0; it < 8; it++) {
      int idx = tid + it * 256;
      int n = idx >> 5, d4l = idx & 31;
      float4 kvv = ksrc[idx];
      int n4 = n >> 2, nl = n & 3;
      int xo = n4 ^ (d4l & 15);
      Kt[((4 * d4l + 0) * 16 + xo) * 4 + nl] = kvv.x;
      Kt[((4 * d4l + 1) * 16 + xo) * 4 + nl] = kvv.y;
      Kt[((4 * d4l + 2) * 16 + xo) * 4 + nl] = kvv.z;
      Kt[((4 * d4l + 3) * 16 + xo) * 4 + nl] = kvv.w;
      Vs4[n * 32 + d4l] = vsrc[idx];
    }
    __syncthreads();

    float4 s4[4];
#pragma unroll
    for (int i = 0; i < 4; i++) s4[i] = make_float4(0.f, 0.f, 0.f, 0.f);
#pragma unroll 4
    for (int d4 = 0; d4 < 32; d4++) {
      int xo = tx ^ (d4 & 15);
      float4 kk0 = Kt4[(4 * d4 + 0) * 16 + xo];
      float4 kk1 = Kt4[(4 * d4 + 1) * 16 + xo];
      float4 kk2 = Kt4[(4 * d4 + 2) * 16 + xo];
      float4 kk3 = Kt4[(4 * d4 + 3) * 16 + xo];
      int qd4 = d4 ^ swzq;
#pragma unroll
      for (int i = 0; i < 4; i++) {
        float4 q4 = Qs4[(4 * ty + i) * 32 + qd4];
        s4[i].x += q4.x * kk0.x + q4.y * kk1.x + q4.z * kk2.x + q4.w * kk3.x;
        s4[i].y += q4.x * kk0.y + q4.y * kk1.y + q4.z * kk2.y + q4.w * kk3.y;
        s4[i].z += q4.x * kk0.z + q4.y * kk1.z + q4.z * kk2.z + q4.w * kk3.z;
        s4[i].w += q4.x * kk0.w + q4.y * kk1.w + q4.z * kk2.w + q4.w * kk3.w;
      }
    }

#pragma unroll
    for (int i = 0; i < 4; i++) {
      float sx = s4[i].x, sy = s4[i].y, sz = s4[i].z, sw = s4[i].w;
      int qrow = qb * 64 + 4 * ty + i;
      if (kb == qb) {
        int kc = kb * 64 + 4 * tx;
        if (kc + 0 > qrow) sx = -1e30f;
        if (kc + 1 > qrow) sy = -1e30f;
        if (kc + 2 > qrow) sz = -1e30f;
        if (kc + 3 > qrow) sw = -1e30f;
      }
      float mx = fmaxf(fmaxf(sx, sy), fmaxf(sz, sw));
#pragma unroll
      for (int o = 8; o; o >>= 1)
        mx = fmaxf(mx, __shfl_xor_sync(0xffffffffu, mx, o));
      float newm = fmaxf(m_r[i], mx);
      float corr = __expf(m_r[i] - newm);
      m_r[i] = newm;
      float px = __expf(sx - newm), py = __expf(sy - newm);
      float pz = __expf(sz - newm), pw = __expf(sw - newm);
      l_r[i] = l_r[i] * corr + (px + py + pz + pw);
#pragma unroll
      for (int j = 0; j < 8; j++) O[i][j] *= corr;
      Ps2[(4 * ty + i) * 33 + 2 * tx] = make_float2(px, py);
      Ps2[(4 * ty + i) * 33 + 2 * tx + 1] = make_float2(pz, pw);
    }
    __syncthreads();

#pragma unroll 8
    for (int k = 0; k < 64; k++) {
      float4 v0 = Vs4[k * 32 + tx];
      float4 v1 = Vs4[k * 32 + 16 + tx];
#pragma unroll
      for (int i = 0; i < 4; i++) {
        float pp = Ps[(4 * ty + i) * 66 + k];
        O[i][0] += pp * v0.x; O[i][1] += pp * v0.y;
        O[i][2] += pp * v0.z; O[i][3] += pp * v0.w;
        O[i][4] += pp * v1.x; O[i][5] += pp * v1.y;
        O[i][6] += pp * v1.z; O[i][7] += pp * v1.w;
      }
    }
  }

#pragma unroll
  for (int i = 0; i < 4; i++) {
    float ls = l_r[i];
#pragma unroll
    for (int o = 8; o; o >>= 1) ls += __shfl_xor_sync(0xffffffffu, ls, o);
    float inv = 1.f / ls;
    int t = qb * 64 + 4 * ty + i;
    float* op = out + ((size_t)b * TSEQ + t) * HD;
    *(float4*)(op + tx * 4) = make_float4(O[i][0] * inv, O[i][1] * inv,
                                          O[i][2] * inv, O[i][3] * inv);
    *(float4*)(op + 64 + tx * 4) = make_float4(O[i][4] * inv, O[i][5] * inv,
                                               O[i][6] * inv, O[i][7] * inv);
  }
}

extern "C" void kernel_launch(void* const* d_in, const int* in_sizes, int n_in,
                              void* d_out, int out_size) {
  (void)in_sizes; (void)n_in; (void)out_size;
  const float* x  = (const float*)d_in[0];
  const float* Wq = (const float*)d_in[1];
  const float* Wk = (const float*)d_in[2];
  const float* Wv = (const float*)d_in[3];
  float* out = (float*)d_out;

  const int SMEMQ = 2 * BUF_B;  // 81920 B
  cudaFuncSetAttribute(qkv_hmma, cudaFuncAttributeMaxDynamicSharedMemorySize,
                       SMEMQ);
  dim3 g1(128, 3);
  qkv_hmma<<<g1, 512, SMEMQ>>>(x, Wq, Wk, Wv);

  const int SMEM = (64 * 128 + 128 * 64 + 64 * 128 + 64 * 66) * 4;  // 115200 B
  cudaFuncSetAttribute(attn_kernel, cudaFuncAttributeMaxDynamicSharedMemorySize,
                       SMEM);
  dim3 g2(32, 8);
  attn_kernel<<<g2, 256, SMEM>>>(out);
}

// round 5
// speedup vs baseline: 3.4703x; 2.6578x over previous
#include <cuda_runtime.h>
#include <cuda_bf16.h>
#include <cstdint>

#define TSEQ 2048
#define BATCH 8
#define DM 1024
#define HD 128
#define MTOT (BATCH * TSEQ)

// bf16 hi/lo scratch for projected Q/K/V. Q pre-scaled by 1/sqrt(HD).
__device__ __align__(16) __nv_bfloat16 g_qh[MTOT * HD];
__device__ __align__(16) __nv_bfloat16 g_ql[MTOT * HD];
__device__ __align__(16) __nv_bfloat16 g_kh[MTOT * HD];
__device__ __align__(16) __nv_bfloat16 g_kl[MTOT * HD];
__device__ __align__(16) __nv_bfloat16 g_vh[MTOT * HD];
__device__ __align__(16) __nv_bfloat16 g_vl[MTOT * HD];

__device__ __forceinline__ uint32_t smem_u32(const void* p) {
  return (uint32_t)__cvta_generic_to_shared(p);
}

__device__ __forceinline__ void mma_bf16(float* d, const uint32_t* a,
                                         const uint32_t* b) {
  asm volatile(
      "mma.sync.aligned.m16n8k16.row.col.f32.bf16.bf16.f32 "
      "{%0,%1,%2,%3}, {%4,%5,%6,%7}, {%8,%9}, {%0,%1,%2,%3};\n"
      : "+f"(d[0]), "+f"(d[1]), "+f"(d[2]), "+f"(d[3])
      : "r"(a[0]), "r"(a[1]), "r"(a[2]), "r"(a[3]), "r"(b[0]), "r"(b[1]));
}

__device__ __forceinline__ void ldm_x4(uint32_t* r, uint32_t addr) {
  asm volatile(
      "ldmatrix.sync.aligned.m8n8.x4.shared.b16 {%0,%1,%2,%3}, [%4];"
      : "=r"(r[0]), "=r"(r[1]), "=r"(r[2]), "=r"(r[3]) : "r"(addr));
}
__device__ __forceinline__ void ldm_x4_t(uint32_t* r, uint32_t addr) {
  asm volatile(
      "ldmatrix.sync.aligned.m8n8.x4.trans.shared.b16 {%0,%1,%2,%3}, [%4];"
      : "=r"(r[0]), "=r"(r[1]), "=r"(r[2]), "=r"(r[3]) : "r"(addr));
}

// Convert 8 fp32 -> 8 bf16 hi + 8 bf16 lo (packed 16B each)
__device__ __forceinline__ void cvt8(float4 a0, float4 a1, uint4& hi, uint4& lo) {
  __nv_bfloat162 h0 = __floats2bfloat162_rn(a0.x, a0.y);
  __nv_bfloat162 h1 = __floats2bfloat162_rn(a0.z, a0.w);
  __nv_bfloat162 h2 = __floats2bfloat162_rn(a1.x, a1.y);
  __nv_bfloat162 h3 = __floats2bfloat162_rn(a1.z, a1.w);
  __nv_bfloat162 l0 = __floats2bfloat162_rn(a0.x - __bfloat162float(h0.x),
                                            a0.y - __bfloat162float(h0.y));
  __nv_bfloat162 l1 = __floats2bfloat162_rn(a0.z - __bfloat162float(h1.x),
                                            a0.w - __bfloat162float(h1.y));
  __nv_bfloat162 l2 = __floats2bfloat162_rn(a1.x - __bfloat162float(h2.x),
                                            a1.y - __bfloat162float(h2.y));
  __nv_bfloat162 l3 = __floats2bfloat162_rn(a1.z - __bfloat162float(h3.x),
                                            a1.w - __bfloat162float(h3.y));
  hi = make_uint4(*(uint32_t*)&h0, *(uint32_t*)&h1, *(uint32_t*)&h2, *(uint32_t*)&h3);
  lo = make_uint4(*(uint32_t*)&l0, *(uint32_t*)&l1, *(uint32_t*)&l2, *(uint32_t*)&l3);
}

// ---------------------------------------------------------------------------
// Kernel 1: QKV projection (bf16 HMMA split-3), writes bf16 hi/lo outputs.
// ---------------------------------------------------------------------------
#define RSTRIDE 80
#define TILE_B (128 * RSTRIDE)
#define BUF_B (4 * TILE_B)

__global__ __launch_bounds__(512) void qkv_hmma(
    const float* __restrict__ x, const float* __restrict__ Wq,
    const float* __restrict__ Wk, const float* __restrict__ Wv) {
  extern __shared__ __align__(1024) char smem[];
  const float* W = (blockIdx.y == 0) ? Wq : (blockIdx.y == 1 ? Wk : Wv);
  __nv_bfloat16* oh = (blockIdx.y == 0) ? g_qh : (blockIdx.y == 1 ? g_kh : g_vh);
  __nv_bfloat16* ol = (blockIdx.y == 0) ? g_ql : (blockIdx.y == 1 ? g_kl : g_vl);

  const int tid = threadIdx.x;
  const int lane = tid & 31, wid = tid >> 5;
  const int wm = wid >> 2, wn = wid & 3;
  const int m0 = blockIdx.x * 128;
  const uint32_t sb = smem_u32(smem);

  const int lrow = tid >> 2, lc = tid & 3;
  const float* aSrc = x + (size_t)(m0 + lrow) * DM + lc * 8;
  const float* bSrc = W + (size_t)lrow * DM + lc * 8;
  const uint32_t stoOff = lrow * RSTRIDE + lc * 16;

  const int lane15 = lane & 15;
  const uint32_t aColOff = (lane >> 4) * 16;
  const uint32_t aRowB = (wm * 32 + lane15) * RSTRIDE;
  const uint32_t bRowB = (wn * 32 + ((lane >> 4) << 3) + (lane & 7)) * RSTRIDE;
  const uint32_t bColOff = ((lane >> 3) & 1) * 16;

  float acc[2][4][4];
#pragma unroll
  for (int i = 0; i < 2; i++)
#pragma unroll
    for (int j = 0; j < 4; j++)
#pragma unroll
      for (int r = 0; r < 4; r++) acc[i][j][r] = 0.f;

  float4 pA0, pA1, pB0, pB1;
  pA0 = *(const float4*)(aSrc);
  pA1 = *(const float4*)(aSrc + 4);
  pB0 = *(const float4*)(bSrc);
  pB1 = *(const float4*)(bSrc + 4);
  {
    uint4 hi, lo;
    char* p = smem + stoOff;
    cvt8(pA0, pA1, hi, lo);
    *(uint4*)(p) = hi;
    *(uint4*)(p + TILE_B) = lo;
    cvt8(pB0, pB1, hi, lo);
    *(uint4*)(p + 2 * TILE_B) = hi;
    *(uint4*)(p + 3 * TILE_B) = lo;
  }
  __syncthreads();

  for (int kt = 0; kt < 32; kt++) {
    if (kt < 31) {
      const float* a = aSrc + (kt + 1) * 32;
      const float* b = bSrc + (kt + 1) * 32;
      pA0 = *(const float4*)(a);
      pA1 = *(const float4*)(a + 4);
      pB0 = *(const float4*)(b);
      pB1 = *(const float4*)(b + 4);
    }
    const uint32_t bufBase = sb + (kt & 1) * BUF_B;
#pragma unroll
    for (int s = 0; s < 2; s++) {
      uint32_t ah[2][4], al[2][4], bh[2][4], bl[2][4];
#pragma unroll
      for (int i = 0; i < 2; i++) {
        uint32_t aa = bufBase + aRowB + i * (16 * RSTRIDE) + s * 32 + aColOff;
        ldm_x4(ah[i], aa);
        ldm_x4(al[i], aa + TILE_B);
      }
#pragma unroll
      for (int j = 0; j < 2; j++) {
        uint32_t ba = bufBase + 2 * TILE_B + bRowB + j * (16 * RSTRIDE) + s * 32 + bColOff;
        ldm_x4(bh[j], ba);
        ldm_x4(bl[j], ba + TILE_B);
      }
#pragma unroll
      for (int i = 0; i < 2; i++)
#pragma unroll
        for (int jj = 0; jj < 4; jj++) {
          const uint32_t* bhp = &bh[jj >> 1][(jj & 1) * 2];
          const uint32_t* blp = &bl[jj >> 1][(jj & 1) * 2];
          mma_bf16(acc[i][jj], ah[i], bhp);
          mma_bf16(acc[i][jj], ah[i], blp);
          mma_bf16(acc[i][jj], al[i], bhp);
        }
    }
    if (kt < 31) {
      char* p = smem + ((kt + 1) & 1) * BUF_B + stoOff;
      uint4 hi, lo;
      cvt8(pA0, pA1, hi, lo);
      *(uint4*)(p) = hi;
      *(uint4*)(p + TILE_B) = lo;
      cvt8(pB0, pB1, hi, lo);
      *(uint4*)(p + 2 * TILE_B) = hi;
      *(uint4*)(p + 3 * TILE_B) = lo;
    }
    __syncthreads();
  }

  const float qs = (blockIdx.y == 0) ? 0.08838834764831845f : 1.0f;
  const int g = lane >> 2, tig = lane & 3;
#pragma unroll
  for (int i = 0; i < 2; i++) {
    int r0 = m0 + wm * 32 + i * 16 + g;
#pragma unroll
    for (int jj = 0; jj < 4; jj++) {
      int col = wn * 32 + jj * 8 + 2 * tig;
      float v0 = acc[i][jj][0] * qs, v1 = acc[i][jj][1] * qs;
      float v2 = acc[i][jj][2] * qs, v3 = acc[i][jj][3] * qs;
      __nv_bfloat162 h01 = __floats2bfloat162_rn(v0, v1);
      __nv_bfloat162 l01 = __floats2bfloat162_rn(v0 - __bfloat162float(h01.x),
                                                 v1 - __bfloat162float(h01.y));
      __nv_bfloat162 h23 = __floats2bfloat162_rn(v2, v3);
      __nv_bfloat162 l23 = __floats2bfloat162_rn(v2 - __bfloat162float(h23.x),
                                                 v3 - __bfloat162float(h23.y));
      *(uint32_t*)&oh[(size_t)r0 * HD + col] = *(uint32_t*)&h01;
      *(uint32_t*)&ol[(size_t)r0 * HD + col] = *(uint32_t*)&l01;
      *(uint32_t*)&oh[(size_t)(r0 + 8) * HD + col] = *(uint32_t*)&h23;
      *(uint32_t*)&ol[(size_t)(r0 + 8) * HD + col] = *(uint32_t*)&l23;
    }
  }
}

// ---------------------------------------------------------------------------
// Kernel 2: causal flash attention with bf16 HMMA (split-3 both matmuls).
// BQ=BKV=64, 256 thr, warp grid 4(m rows)x2(col halves). Paired q-tiles
// (bidx, 31-bidx) -> 33 kv-iters per CTA, grid (16,8) = 128 CTAs = 1 wave.
// ---------------------------------------------------------------------------
#define QSTR 272  // bytes per 128-col bf16 row (128*2 + 16 pad)
#define PSTR 144  // bytes per 64-col bf16 row (64*2 + 16 pad)
#define OFF_QH 0
#define OFF_QL 17408
#define OFF_KH 34816
#define OFF_KL 52224
#define OFF_VH 69632
#define OFF_VL 87040
#define OFF_PH 104448
#define OFF_PL 113664
#define OFF_MS 122880
#define ATT_SMEM 123392

__global__ __launch_bounds__(256) void attn_mma(float* __restrict__ out) {
  extern __shared__ __align__(16) char smA[];
  const uint32_t sb = smem_u32(smA);
  float* msm = (float*)(smA + OFF_MS);  // [64][2]

  const int tid = threadIdx.x, lane = tid & 31, wid = tid >> 5;
  const int wm = wid & 3, wh = wid >> 2;
  const int g = lane >> 2, tig = lane & 3;
  const int b = blockIdx.y;

  const int aRow = lane & 15;
  const int aCol = (lane >> 4) * 16;
  const int bRow = ((lane >> 4) << 3) + (lane & 7);
  const int bCol = ((lane >> 3) & 1) * 16;
  const int vRow = (lane & 7) + (((lane >> 3) & 1) << 3);
  const int vCol = (lane >> 4) * 8;
  const int rA = 16 * wm + g;  // local q-row (and rA+8)

  for (int phse = 0; phse < 2; phse++) {
    const int qt = phse ? (31 - blockIdx.x) : blockIdx.x;
    const size_t qoff = ((size_t)b * TSEQ + (size_t)qt * 64) * HD;
    __syncthreads();
    {
      const uint4* shp = (const uint4*)(g_qh + qoff);
      const uint4* slp = (const uint4*)(g_ql + qoff);
#pragma unroll
      for (int it = 0; it < 4; it++) {
        int idx = tid + it * 256;
        uint32_t d = (idx >> 4) * QSTR + (idx & 15) * 16;
        *(uint4*)(smA + OFF_QH + d) = shp[idx];
        *(uint4*)(smA + OFF_QL + d) = slp[idx];
      }
    }
    __syncthreads();

    uint32_t qfh[8][4], qfl[8][4];
#pragma unroll
    for (int c = 0; c < 8; c++) {
      uint32_t ad = sb + OFF_QH + (16 * wm + aRow) * QSTR + c * 32 + aCol;
      ldm_x4(qfh[c], ad);
      ldm_x4(qfl[c], ad + (OFF_QL - OFF_QH));
    }

    float O[8][4];
#pragma unroll
    for (int nt = 0; nt < 8; nt++)
#pragma unroll
      for (int r = 0; r < 4; r++) O[nt][r] = 0.f;
    float m_r[2] = {-1e30f, -1e30f}, l_r[2] = {0.f, 0.f};

    for (int kb = 0; kb <= qt; kb++) {
      const size_t koff = ((size_t)b * TSEQ + (size_t)kb * 64) * HD;
      __syncthreads();
      {
        const uint4* kh = (const uint4*)(g_kh + koff);
        const uint4* kl = (const uint4*)(g_kl + koff);
        const uint4* vh = (const uint4*)(g_vh + koff);
        const uint4* vl = (const uint4*)(g_vl + koff);
#pragma unroll
        for (int it = 0; it < 4; it++) {
          int idx = tid + it * 256;
          uint32_t d = (idx >> 4) * QSTR + (idx & 15) * 16;
          *(uint4*)(smA + OFF_KH + d) = kh[idx];
          *(uint4*)(smA + OFF_KL + d) = kl[idx];
          *(uint4*)(smA + OFF_VH + d) = vh[idx];
          *(uint4*)(smA + OFF_VL + d) = vl[idx];
        }
      }
      __syncthreads();

      // ---- S = Q K^T (split-3) ----
      float sfr[4][4];
#pragma unroll
      for (int nt = 0; nt < 4; nt++)
#pragma unroll
        for (int r = 0; r < 4; r++) sfr[nt][r] = 0.f;
#pragma unroll
      for (int c = 0; c < 8; c++) {
#pragma unroll
        for (int pn = 0; pn < 2; pn++) {
          uint32_t kh4[4], kl4[4];
          uint32_t ad = sb + OFF_KH + (32 * wh + 16 * pn + bRow) * QSTR + c * 32 + bCol;
          ldm_x4(kh4, ad);
          ldm_x4(kl4, ad + (OFF_KL - OFF_KH));
#pragma unroll
          for (int h = 0; h < 2; h++) {
            int nt = 2 * pn + h;
            mma_bf16(sfr[nt], qfh[c], &kh4[2 * h]);
            mma_bf16(sfr[nt], qfh[c], &kl4[2 * h]);
            mma_bf16(sfr[nt], qfl[c], &kh4[2 * h]);
          }
        }
      }

      // ---- causal mask on diagonal tile ----
      if (kb == qt) {
#pragma unroll
        for (int nt = 0; nt < 4; nt++) {
          int colRel = 32 * wh + 8 * nt + 2 * tig;
          if (colRel > rA) sfr[nt][0] = -1e30f;
          if (colRel + 1 > rA) sfr[nt][1] = -1e30f;
          if (colRel > rA + 8) sfr[nt][2] = -1e30f;
          if (colRel + 1 > rA + 8) sfr[nt][3] = -1e30f;
        }
      }

      // ---- half-row maxes, cross-warp exchange ----
      float mxA = fmaxf(fmaxf(sfr[0][0], sfr[0][1]), fmaxf(sfr[1][0], sfr[1][1]));
      mxA = fmaxf(mxA, fmaxf(fmaxf(sfr[2][0], sfr[2][1]), fmaxf(sfr[3][0], sfr[3][1])));
      float mxB = fmaxf(fmaxf(sfr[0][2], sfr[0][3]), fmaxf(sfr[1][2], sfr[1][3]));
      mxB = fmaxf(mxB, fmaxf(fmaxf(sfr[2][2], sfr[2][3]), fmaxf(sfr[3][2], sfr[3][3])));
#pragma unroll
      for (int o = 1; o <= 2; o <<= 1) {
        mxA = fmaxf(mxA, __shfl_xor_sync(0xffffffffu, mxA, o));
        mxB = fmaxf(mxB, __shfl_xor_sync(0xffffffffu, mxB, o));
      }
      if (tig == 0) {
        msm[rA * 2 + wh] = mxA;
        msm[(rA + 8) * 2 + wh] = mxB;
      }
      __syncthreads();
      float nmA = fmaxf(m_r[0], fmaxf(msm[rA * 2], msm[rA * 2 + 1]));
      float nmB = fmaxf(m_r[1], fmaxf(msm[(rA + 8) * 2], msm[(rA + 8) * 2 + 1]));
      float corrA = __expf(m_r[0] - nmA);
      float corrB = __expf(m_r[1] - nmB);
      m_r[0] = nmA;
      m_r[1] = nmB;

      // ---- p = exp(s - m), store bf16 hi/lo, partial sums ----
      float sumA = 0.f, sumB = 0.f;
#pragma unroll
      for (int nt = 0; nt < 4; nt++) {
        float pa0 = __expf(sfr[nt][0] - nmA), pa1 = __expf(sfr[nt][1] - nmA);
        float pb0 = __expf(sfr[nt][2] - nmB), pb1 = __expf(sfr[nt][3] - nmB);
        sumA += pa0 + pa1;
        sumB += pb0 + pb1;
        int colb = (32 * wh + 8 * nt + 2 * tig) * 2;
        __nv_bfloat162 ha = __floats2bfloat162_rn(pa0, pa1);
        __nv_bfloat162 la = __floats2bfloat162_rn(pa0 - __bfloat162float(ha.x),
                                                  pa1 - __bfloat162float(ha.y));
        __nv_bfloat162 hb = __floats2bfloat162_rn(pb0, pb1);
        __nv_bfloat162 lb = __floats2bfloat162_rn(pb0 - __bfloat162float(hb.x),
                                                  pb1 - __bfloat162float(hb.y));
        *(uint32_t*)(smA + OFF_PH + rA * PSTR + colb) = *(uint32_t*)&ha;
        *(uint32_t*)(smA + OFF_PL + rA * PSTR + colb) = *(uint32_t*)&la;
        *(uint32_t*)(smA + OFF_PH + (rA + 8) * PSTR + colb) = *(uint32_t*)&hb;
        *(uint32_t*)(smA + OFF_PL + (rA + 8) * PSTR + colb) = *(uint32_t*)&lb;
      }
#pragma unroll
      for (int o = 1; o <= 2; o <<= 1) {
        sumA += __shfl_xor_sync(0xffffffffu, sumA, o);
        sumB += __shfl_xor_sync(0xffffffffu, sumB, o);
      }
      l_r[0] = l_r[0] * corrA + sumA;
      l_r[1] = l_r[1] * corrB + sumB;
#pragma unroll
      for (int nt = 0; nt < 8; nt++) {
        O[nt][0] *= corrA;
        O[nt][1] *= corrA;
        O[nt][2] *= corrB;
        O[nt][3] *= corrB;
      }
      __syncthreads();

      // ---- O += P V (split-3) ----
#pragma unroll
      for (int ck = 0; ck < 4; ck++) {
        uint32_t pfh[4], pfl[4];
        uint32_t ad = sb + OFF_PH + (16 * wm + aRow) * PSTR + ck * 32 + aCol;
        ldm_x4(pfh, ad);
        ldm_x4(pfl, ad + (OFF_PL - OFF_PH));
#pragma unroll
        for (int pv = 0; pv < 4; pv++) {
          uint32_t vh4[4], vl4[4];
          uint32_t vd = sb + OFF_VH + (16 * ck + vRow) * QSTR +
                        (64 * wh + 16 * pv + vCol) * 2;
          ldm_x4_t(vh4, vd);
          ldm_x4_t(vl4, vd + (OFF_VL - OFF_VH));
#pragma unroll
          for (int h = 0; h < 2; h++) {
            int nt = 2 * pv + h;
            mma_bf16(O[nt], pfh, &vh4[2 * h]);
            mma_bf16(O[nt], pfh, &vl4[2 * h]);
            mma_bf16(O[nt], pfl, &vh4[2 * h]);
          }
        }
      }
    }

    // ---- epilogue: combine l across halves, normalize, write ----
    __syncthreads();
    if (tig == 0) {
      msm[rA * 2 + wh] = l_r[0];
      msm[(rA + 8) * 2 + wh] = l_r[1];
    }
    __syncthreads();
    float liA = 1.f / (msm[rA * 2] + msm[rA * 2 + 1]);
    float liB = 1.f / (msm[(rA + 8) * 2] + msm[(rA + 8) * 2 + 1]);
    const size_t tA = (size_t)b * TSEQ + qt * 64 + rA;
#pragma unroll
    for (int nt = 0; nt < 8; nt++) {
      int col = 64 * wh + 8 * nt + 2 * tig;
      *(float2*)&out[tA * HD + col] = make_float2(O[nt][0] * liA, O[nt][1] * liA);
      *(float2*)&out[(tA + 8) * HD + col] =
          make_float2(O[nt][2] * liB, O[nt][3] * liB);
    }
  }
}

extern "C" void kernel_launch(void* const* d_in, const int* in_sizes, int n_in,
                              void* d_out, int out_size) {
  (void)in_sizes; (void)n_in; (void)out_size;
  const float* x  = (const float*)d_in[0];
  const float* Wq = (const float*)d_in[1];
  const float* Wk = (const float*)d_in[2];
  const float* Wv = (const float*)d_in[3];
  float* out = (float*)d_out;

  const int SMEMQ = 2 * BUF_B;  // 81920 B
  cudaFuncSetAttribute(qkv_hmma, cudaFuncAttributeMaxDynamicSharedMemorySize,
                       SMEMQ);
  dim3 g1(128, 3);
  qkv_hmma<<<g1, 512, SMEMQ>>>(x, Wq, Wk, Wv);

  cudaFuncSetAttribute(attn_mma, cudaFuncAttributeMaxDynamicSharedMemorySize,
                       ATT_SMEM);
  dim3 g2(16, 8);
  attn_mma<<<g2, 256, ATT_SMEM>>>(out);
}

// round 6
// speedup vs baseline: 3.4910x; 1.0060x over previous
#include <cuda_runtime.h>
#include <cuda_bf16.h>
#include <cstdint>

#define TSEQ 2048
#define BATCH 8
#define DM 1024
#define HD 128
#define MTOT (BATCH * TSEQ)

// bf16 hi/lo scratch for projected Q/K/V. Q pre-scaled by 1/sqrt(HD).
__device__ __align__(16) __nv_bfloat16 g_qh[MTOT * HD];
__device__ __align__(16) __nv_bfloat16 g_ql[MTOT * HD];
__device__ __align__(16) __nv_bfloat16 g_kh[MTOT * HD];
__device__ __align__(16) __nv_bfloat16 g_kl[MTOT * HD];
__device__ __align__(16) __nv_bfloat16 g_vh[MTOT * HD];
__device__ __align__(16) __nv_bfloat16 g_vl[MTOT * HD];

__device__ __forceinline__ uint32_t smem_u32(const void* p) {
  return (uint32_t)__cvta_generic_to_shared(p);
}

__device__ __forceinline__ void mma_bf16(float* d, const uint32_t* a,
                                         const uint32_t* b) {
  asm volatile(
      "mma.sync.aligned.m16n8k16.row.col.f32.bf16.bf16.f32 "
      "{%0,%1,%2,%3}, {%4,%5,%6,%7}, {%8,%9}, {%0,%1,%2,%3};\n"
      : "+f"(d[0]), "+f"(d[1]), "+f"(d[2]), "+f"(d[3])
      : "r"(a[0]), "r"(a[1]), "r"(a[2]), "r"(a[3]), "r"(b[0]), "r"(b[1]));
}

__device__ __forceinline__ void ldm_x4(uint32_t* r, uint32_t addr) {
  asm volatile(
      "ldmatrix.sync.aligned.m8n8.x4.shared.b16 {%0,%1,%2,%3}, [%4];"
      : "=r"(r[0]), "=r"(r[1]), "=r"(r[2]), "=r"(r[3]) : "r"(addr));
}
__device__ __forceinline__ void ldm_x4_t(uint32_t* r, uint32_t addr) {
  asm volatile(
      "ldmatrix.sync.aligned.m8n8.x4.trans.shared.b16 {%0,%1,%2,%3}, [%4];"
      : "=r"(r[0]), "=r"(r[1]), "=r"(r[2]), "=r"(r[3]) : "r"(addr));
}

#define CP16(dst, src) \
  asm volatile("cp.async.cg.shared.global [%0], [%1], 16;" :: "r"(dst), "l"(src))
#define CP_COMMIT() asm volatile("cp.async.commit_group;" ::: "memory")
#define CP_WAIT0() asm volatile("cp.async.wait_group 0;" ::: "memory")
#define CP_WAIT1() asm volatile("cp.async.wait_group 1;" ::: "memory")

// Convert 8 fp32 -> 8 bf16 hi + 8 bf16 lo (packed 16B each)
__device__ __forceinline__ void cvt8(float4 a0, float4 a1, uint4& hi, uint4& lo) {
  __nv_bfloat162 h0 = __floats2bfloat162_rn(a0.x, a0.y);
  __nv_bfloat162 h1 = __floats2bfloat162_rn(a0.z, a0.w);
  __nv_bfloat162 h2 = __floats2bfloat162_rn(a1.x, a1.y);
  __nv_bfloat162 h3 = __floats2bfloat162_rn(a1.z, a1.w);
  __nv_bfloat162 l0 = __floats2bfloat162_rn(a0.x - __bfloat162float(h0.x),
                                            a0.y - __bfloat162float(h0.y));
  __nv_bfloat162 l1 = __floats2bfloat162_rn(a0.z - __bfloat162float(h1.x),
                                            a0.w - __bfloat162float(h1.y));
  __nv_bfloat162 l2 = __floats2bfloat162_rn(a1.x - __bfloat162float(h2.x),
                                            a1.y - __bfloat162float(h2.y));
  __nv_bfloat162 l3 = __floats2bfloat162_rn(a1.z - __bfloat162float(h3.x),
                                            a1.w - __bfloat162float(h3.y));
  hi = make_uint4(*(uint32_t*)&h0, *(uint32_t*)&h1, *(uint32_t*)&h2, *(uint32_t*)&h3);
  lo = make_uint4(*(uint32_t*)&l0, *(uint32_t*)&l1, *(uint32_t*)&l2, *(uint32_t*)&l3);
}

// ---------------------------------------------------------------------------
// Kernel 1: QKV projection (bf16 HMMA split-3), writes bf16 hi/lo outputs.
// ---------------------------------------------------------------------------
#define RSTRIDE 80
#define TILE_B (128 * RSTRIDE)
#define BUF_B (4 * TILE_B)

__global__ __launch_bounds__(512) void qkv_hmma(
    const float* __restrict__ x, const float* __restrict__ Wq,
    const float* __restrict__ Wk, const float* __restrict__ Wv) {
  extern __shared__ __align__(1024) char smem[];
  const float* W = (blockIdx.y == 0) ? Wq : (blockIdx.y == 1 ? Wk : Wv);
  __nv_bfloat16* oh = (blockIdx.y == 0) ? g_qh : (blockIdx.y == 1 ? g_kh : g_vh);
  __nv_bfloat16* ol = (blockIdx.y == 0) ? g_ql : (blockIdx.y == 1 ? g_kl : g_vl);

  const int tid = threadIdx.x;
  const int lane = tid & 31, wid = tid >> 5;
  const int wm = wid >> 2, wn = wid & 3;
  const int m0 = blockIdx.x * 128;
  const uint32_t sb = smem_u32(smem);

  const int lrow = tid >> 2, lc = tid & 3;
  const float* aSrc = x + (size_t)(m0 + lrow) * DM + lc * 8;
  const float* bSrc = W + (size_t)lrow * DM + lc * 8;
  const uint32_t stoOff = lrow * RSTRIDE + lc * 16;

  const int lane15 = lane & 15;
  const uint32_t aColOff = (lane >> 4) * 16;
  const uint32_t aRowB = (wm * 32 + lane15) * RSTRIDE;
  const uint32_t bRowB = (wn * 32 + ((lane >> 4) << 3) + (lane & 7)) * RSTRIDE;
  const uint32_t bColOff = ((lane >> 3) & 1) * 16;

  float acc[2][4][4];
#pragma unroll
  for (int i = 0; i < 2; i++)
#pragma unroll
    for (int j = 0; j < 4; j++)
#pragma unroll
      for (int r = 0; r < 4; r++) acc[i][j][r] = 0.f;

  float4 pA0, pA1, pB0, pB1;
  pA0 = *(const float4*)(aSrc);
  pA1 = *(const float4*)(aSrc + 4);
  pB0 = *(const float4*)(bSrc);
  pB1 = *(const float4*)(bSrc + 4);
  {
    uint4 hi, lo;
    char* p = smem + stoOff;
    cvt8(pA0, pA1, hi, lo);
    *(uint4*)(p) = hi;
    *(uint4*)(p + TILE_B) = lo;
    cvt8(pB0, pB1, hi, lo);
    *(uint4*)(p + 2 * TILE_B) = hi;
    *(uint4*)(p + 3 * TILE_B) = lo;
  }
  __syncthreads();

  for (int kt = 0; kt < 32; kt++) {
    if (kt < 31) {
      const float* a = aSrc + (kt + 1) * 32;
      const float* b = bSrc + (kt + 1) * 32;
      pA0 = *(const float4*)(a);
      pA1 = *(const float4*)(a + 4);
      pB0 = *(const float4*)(b);
      pB1 = *(const float4*)(b + 4);
    }
    const uint32_t bufBase = sb + (kt & 1) * BUF_B;
#pragma unroll
    for (int s = 0; s < 2; s++) {
      uint32_t ah[2][4], al[2][4], bh[2][4], bl[2][4];
#pragma unroll
      for (int i = 0; i < 2; i++) {
        uint32_t aa = bufBase + aRowB + i * (16 * RSTRIDE) + s * 32 + aColOff;
        ldm_x4(ah[i], aa);
        ldm_x4(al[i], aa + TILE_B);
      }
#pragma unroll
      for (int j = 0; j < 2; j++) {
        uint32_t ba = bufBase + 2 * TILE_B + bRowB + j * (16 * RSTRIDE) + s * 32 + bColOff;
        ldm_x4(bh[j], ba);
        ldm_x4(bl[j], ba + TILE_B);
      }
#pragma unroll
      for (int i = 0; i < 2; i++)
#pragma unroll
        for (int jj = 0; jj < 4; jj++) {
          const uint32_t* bhp = &bh[jj >> 1][(jj & 1) * 2];
          const uint32_t* blp = &bl[jj >> 1][(jj & 1) * 2];
          mma_bf16(acc[i][jj], ah[i], bhp);
          mma_bf16(acc[i][jj], ah[i], blp);
          mma_bf16(acc[i][jj], al[i], bhp);
        }
    }
    if (kt < 31) {
      char* p = smem + ((kt + 1) & 1) * BUF_B + stoOff;
      uint4 hi, lo;
      cvt8(pA0, pA1, hi, lo);
      *(uint4*)(p) = hi;
      *(uint4*)(p + TILE_B) = lo;
      cvt8(pB0, pB1, hi, lo);
      *(uint4*)(p + 2 * TILE_B) = hi;
      *(uint4*)(p + 3 * TILE_B) = lo;
    }
    __syncthreads();
  }

  const float qs = (blockIdx.y == 0) ? 0.08838834764831845f : 1.0f;
  const int g = lane >> 2, tig = lane & 3;
#pragma unroll
  for (int i = 0; i < 2; i++) {
    int r0 = m0 + wm * 32 + i * 16 + g;
#pragma unroll
    for (int jj = 0; jj < 4; jj++) {
      int col = wn * 32 + jj * 8 + 2 * tig;
      float v0 = acc[i][jj][0] * qs, v1 = acc[i][jj][1] * qs;
      float v2 = acc[i][jj][2] * qs, v3 = acc[i][jj][3] * qs;
      __nv_bfloat162 h01 = __floats2bfloat162_rn(v0, v1);
      __nv_bfloat162 l01 = __floats2bfloat162_rn(v0 - __bfloat162float(h01.x),
                                                 v1 - __bfloat162float(h01.y));
      __nv_bfloat162 h23 = __floats2bfloat162_rn(v2, v3);
      __nv_bfloat162 l23 = __floats2bfloat162_rn(v2 - __bfloat162float(h23.x),
                                                 v3 - __bfloat162float(h23.y));
      *(uint32_t*)&oh[(size_t)r0 * HD + col] = *(uint32_t*)&h01;
      *(uint32_t*)&ol[(size_t)r0 * HD + col] = *(uint32_t*)&l01;
      *(uint32_t*)&oh[(size_t)(r0 + 8) * HD + col] = *(uint32_t*)&h23;
      *(uint32_t*)&ol[(size_t)(r0 + 8) * HD + col] = *(uint32_t*)&l23;
    }
  }
}

// ---------------------------------------------------------------------------
// Kernel 2: causal flash attention, bf16 HMMA split-3, cp.async double-
// buffered KV. BQ=BKV=64, 256 thr, warp grid 4(m)x2(n-half). Paired q-tiles
// (bidx, 31-bidx): 33 kv-iters/CTA, grid (16,8) = 128 CTAs = 1 wave.
// ---------------------------------------------------------------------------
#define QSTR 272           // bytes per 128-col bf16 row
#define PSTR 144           // bytes per 64-col bf16 row
#define KVB 17408          // one array (64 rows x QSTR)
#define KVBUF 69632        // KH,KL,VH,VL
#define OFF_P (2 * KVBUF)  // 139264
#define OFF_PL (OFF_P + 9216)
#define OFF_MS (OFF_P + 18432)
#define ATT_SMEM (OFF_MS + 512)  // 158208

__global__ __launch_bounds__(256) void attn_mma(float* __restrict__ out) {
  extern __shared__ __align__(16) char smA[];
  const uint32_t sb = smem_u32(smA);
  float* msm = (float*)(smA + OFF_MS);  // [64][2]

  const int tid = threadIdx.x, lane = tid & 31, wid = tid >> 5;
  const int wm = wid & 3, wh = wid >> 2;
  const int g = lane >> 2, tig = lane & 3;
  const int b = blockIdx.y;

  const int aRow = lane & 15;
  const int aCol = (lane >> 4) * 16;
  const int bRow = ((lane >> 4) << 3) + (lane & 7);
  const int bCol = ((lane >> 3) & 1) * 16;
  const int vRow = (lane & 7) + (((lane >> 3) & 1) << 3);
  const int vCol = (lane >> 4) * 8;
  const int rA = 16 * wm + g;

  // per-thread load-role constants (16B chunks)
  const int ldRow = tid >> 4, ldC = tid & 15;              // row 0..15 (x4), chunk
  const uint32_t ldDst = ldRow * QSTR + ldC * 16;          // + it*16*QSTR
  const size_t ldSrc = (size_t)ldRow * HD + ldC * 8;       // bf16 elems

  for (int phse = 0; phse < 2; phse++) {
    const int qt = phse ? (31 - blockIdx.x) : blockIdx.x;
    const size_t qoff = ((size_t)b * TSEQ + (size_t)qt * 64) * HD;
    __syncthreads();  // prev phase fully done before reusing buffers
    // ---- stage Q through buffer 1's KH/KL region ----
    {
      const uint4* shp = (const uint4*)(g_qh + qoff);
      const uint4* slp = (const uint4*)(g_ql + qoff);
#pragma unroll
      for (int it = 0; it < 4; it++) {
        int idx = tid + it * 256;
        uint32_t d = (idx >> 4) * QSTR + (idx & 15) * 16;
        *(uint4*)(smA + KVBUF + d) = shp[idx];
        *(uint4*)(smA + KVBUF + KVB + d) = slp[idx];
      }
    }
    __syncthreads();

    uint32_t qfh[8][4], qfl[8][4];
#pragma unroll
    for (int c = 0; c < 8; c++) {
      uint32_t ad = sb + KVBUF + (16 * wm + aRow) * QSTR + c * 32 + aCol;
      ldm_x4(qfh[c], ad);
      ldm_x4(qfl[c], ad + KVB);
    }
    __syncthreads();  // all warps done reading Q staging before kb=1 overwrites

    // ---- prologue: async-copy KV tile 0 into buffer 0 ----
    {
      const size_t koff = (size_t)b * TSEQ * HD;
#pragma unroll
      for (int it = 0; it < 4; it++) {
        uint32_t d = sb + ldDst + it * (16 * QSTR);
        size_t s = koff + ldSrc + (size_t)it * 16 * HD;
        CP16(d + 0 * KVB, g_kh + s);
        CP16(d + 1 * KVB, g_kl + s);
        CP16(d + 2 * KVB, g_vh + s);
        CP16(d + 3 * KVB, g_vl + s);
      }
      CP_COMMIT();
    }

    float O[8][4];
#pragma unroll
    for (int nt = 0; nt < 8; nt++)
#pragma unroll
      for (int r = 0; r < 4; r++) O[nt][r] = 0.f;
    float m_r[2] = {-1e30f, -1e30f}, l_r[2] = {0.f, 0.f};

    for (int kb = 0; kb <= qt; kb++) {
      const uint32_t kvb = sb + (kb & 1) * KVBUF;
      // issue next tile's copies into the other buffer (safe: prev-iter
      // consumers of that buffer passed the loop-end syncthreads)
      if (kb < qt) {
        const size_t koff = ((size_t)b * TSEQ + (size_t)(kb + 1) * 64) * HD;
        const uint32_t ob = sb + ((kb + 1) & 1) * KVBUF;
#pragma unroll
        for (int it = 0; it < 4; it++) {
          uint32_t d = ob + ldDst + it * (16 * QSTR);
          size_t s = koff + ldSrc + (size_t)it * 16 * HD;
          CP16(d + 0 * KVB, g_kh + s);
          CP16(d + 1 * KVB, g_kl + s);
          CP16(d + 2 * KVB, g_vh + s);
          CP16(d + 3 * KVB, g_vl + s);
        }
        CP_COMMIT();
        CP_WAIT1();  // current tile's group done; next may fly
      } else {
        CP_WAIT0();
      }
      __syncthreads();  // current KV visible to all warps

      // ---- S = Q K^T (split-3) ----
      float sfr[4][4];
#pragma unroll
      for (int nt = 0; nt < 4; nt++)
#pragma unroll
        for (int r = 0; r < 4; r++) sfr[nt][r] = 0.f;
#pragma unroll
      for (int c = 0; c < 8; c++) {
#pragma unroll
        for (int pn = 0; pn < 2; pn++) {
          uint32_t kh4[4], kl4[4];
          uint32_t ad = kvb + (32 * wh + 16 * pn + bRow) * QSTR + c * 32 + bCol;
          ldm_x4(kh4, ad);
          ldm_x4(kl4, ad + KVB);
#pragma unroll
          for (int h = 0; h < 2; h++) {
            int nt = 2 * pn + h;
            mma_bf16(sfr[nt], qfh[c], &kh4[2 * h]);
            mma_bf16(sfr[nt], qfh[c], &kl4[2 * h]);
            mma_bf16(sfr[nt], qfl[c], &kh4[2 * h]);
          }
        }
      }

      if (kb == qt) {
#pragma unroll
        for (int nt = 0; nt < 4; nt++) {
          int colRel = 32 * wh + 8 * nt + 2 * tig;
          if (colRel > rA) sfr[nt][0] = -1e30f;
          if (colRel + 1 > rA) sfr[nt][1] = -1e30f;
          if (colRel > rA + 8) sfr[nt][2] = -1e30f;
          if (colRel + 1 > rA + 8) sfr[nt][3] = -1e30f;
        }
      }

      // ---- half-row maxes, cross-warp exchange ----
      float mxA = fmaxf(fmaxf(sfr[0][0], sfr[0][1]), fmaxf(sfr[1][0], sfr[1][1]));
      mxA = fmaxf(mxA, fmaxf(fmaxf(sfr[2][0], sfr[2][1]), fmaxf(sfr[3][0], sfr[3][1])));
      float mxB = fmaxf(fmaxf(sfr[0][2], sfr[0][3]), fmaxf(sfr[1][2], sfr[1][3]));
      mxB = fmaxf(mxB, fmaxf(fmaxf(sfr[2][2], sfr[2][3]), fmaxf(sfr[3][2], sfr[3][3])));
#pragma unroll
      for (int o = 1; o <= 2; o <<= 1) {
        mxA = fmaxf(mxA, __shfl_xor_sync(0xffffffffu, mxA, o));
        mxB = fmaxf(mxB, __shfl_xor_sync(0xffffffffu, mxB, o));
      }
      if (tig == 0) {
        msm[rA * 2 + wh] = mxA;
        msm[(rA + 8) * 2 + wh] = mxB;
      }
      __syncthreads();
      float nmA = fmaxf(m_r[0], fmaxf(msm[rA * 2], msm[rA * 2 + 1]));
      float nmB = fmaxf(m_r[1], fmaxf(msm[(rA + 8) * 2], msm[(rA + 8) * 2 + 1]));
      float corrA = __expf(m_r[0] - nmA);
      float corrB = __expf(m_r[1] - nmB);
      m_r[0] = nmA;
      m_r[1] = nmB;

      float sumA = 0.f, sumB = 0.f;
#pragma unroll
      for (int nt = 0; nt < 4; nt++) {
        float pa0 = __expf(sfr[nt][0] - nmA), pa1 = __expf(sfr[nt][1] - nmA);
        float pb0 = __expf(sfr[nt][2] - nmB), pb1 = __expf(sfr[nt][3] - nmB);
        sumA += pa0 + pa1;
        sumB += pb0 + pb1;
        int colb = (32 * wh + 8 * nt + 2 * tig) * 2;
        __nv_bfloat162 ha = __floats2bfloat162_rn(pa0, pa1);
        __nv_bfloat162 la = __floats2bfloat162_rn(pa0 - __bfloat162float(ha.x),
                                                  pa1 - __bfloat162float(ha.y));
        __nv_bfloat162 hb = __floats2bfloat162_rn(pb0, pb1);
        __nv_bfloat162 lb = __floats2bfloat162_rn(pb0 - __bfloat162float(hb.x),
                                                  pb1 - __bfloat162float(hb.y));
        *(uint32_t*)(smA + OFF_P + rA * PSTR + colb) = *(uint32_t*)&ha;
        *(uint32_t*)(smA + OFF_PL + rA * PSTR + colb) = *(uint32_t*)&la;
        *(uint32_t*)(smA + OFF_P + (rA + 8) * PSTR + colb) = *(uint32_t*)&hb;
        *(uint32_t*)(smA + OFF_PL + (rA + 8) * PSTR + colb) = *(uint32_t*)&lb;
      }
#pragma unroll
      for (int o = 1; o <= 2; o <<= 1) {
        sumA += __shfl_xor_sync(0xffffffffu, sumA, o);
        sumB += __shfl_xor_sync(0xffffffffu, sumB, o);
      }
      l_r[0] = l_r[0] * corrA + sumA;
      l_r[1] = l_r[1] * corrB + sumB;
#pragma unroll
      for (int nt = 0; nt < 8; nt++) {
        O[nt][0] *= corrA;
        O[nt][1] *= corrA;
        O[nt][2] *= corrB;
        O[nt][3] *= corrB;
      }
      __syncthreads();  // P visible; also gates buffer reuse next iter

      // ---- O += P V (split-3) ----
#pragma unroll
      for (int ck = 0; ck < 4; ck++) {
        uint32_t pfh[4], pfl[4];
        uint32_t ad = sb + OFF_P + (16 * wm + aRow) * PSTR + ck * 32 + aCol;
        ldm_x4(pfh, ad);
        ldm_x4(pfl, ad + 9216);
#pragma unroll
        for (int pv = 0; pv < 4; pv++) {
          uint32_t vh4[4], vl4[4];
          uint32_t vd = kvb + 2 * KVB + (16 * ck + vRow) * QSTR +
                        (64 * wh + 16 * pv + vCol) * 2;
          ldm_x4_t(vh4, vd);
          ldm_x4_t(vl4, vd + KVB);
#pragma unroll
          for (int h = 0; h < 2; h++) {
            int nt = 2 * pv + h;
            mma_bf16(O[nt], pfh, &vh4[2 * h]);
            mma_bf16(O[nt], pfh, &vl4[2 * h]);
            mma_bf16(O[nt], pfl, &vh4[2 * h]);
          }
        }
      }
      __syncthreads();  // all V reads done before next iter's cp.async lands
    }

    // ---- epilogue ----
    if (tig == 0) {
      msm[rA * 2 + wh] = l_r[0];
      msm[(rA + 8) * 2 + wh] = l_r[1];
    }
    __syncthreads();
    float liA = 1.f / (msm[rA * 2] + msm[rA * 2 + 1]);
    float liB = 1.f / (msm[(rA + 8) * 2] + msm[(rA + 8) * 2 + 1]);
    const size_t tA = (size_t)b * TSEQ + qt * 64 + rA;
#pragma unroll
    for (int nt = 0; nt < 8; nt++) {
      int col = 64 * wh + 8 * nt + 2 * tig;
      *(float2*)&out[tA * HD + col] = make_float2(O[nt][0] * liA, O[nt][1] * liA);
      *(float2*)&out[(tA + 8) * HD + col] =
          make_float2(O[nt][2] * liB, O[nt][3] * liB);
    }
  }
}

extern "C" void kernel_launch(void* const* d_in, const int* in_sizes, int n_in,
                              void* d_out, int out_size) {
  (void)in_sizes; (void)n_in; (void)out_size;
  const float* x  = (const float*)d_in[0];
  const float* Wq = (const float*)d_in[1];
  const float* Wk = (const float*)d_in[2];
  const float* Wv = (const float*)d_in[3];
  float* out = (float*)d_out;

  const int SMEMQ = 2 * BUF_B;  // 81920 B
  cudaFuncSetAttribute(qkv_hmma, cudaFuncAttributeMaxDynamicSharedMemorySize,
                       SMEMQ);
  dim3 g1(128, 3);
  qkv_hmma<<<g1, 512, SMEMQ>>>(x, Wq, Wk, Wv);

  cudaFuncSetAttribute(attn_mma, cudaFuncAttributeMaxDynamicSharedMemorySize,
                       ATT_SMEM);
  dim3 g2(16, 8);
  attn_mma<<<g2, 256, ATT_SMEM>>>(out);
}

// round 7
// speedup vs baseline: 3.8455x; 1.1015x over previous
#include <cuda_runtime.h>
#include <cuda_fp16.h>
#include <cuda_bf16.h>
#include <cstdint>

#define TSEQ 2048
#define BATCH 8
#define DM 1024
#define HD 128
#define MTOT (BATCH * TSEQ)

// fp16 scratch: Q split-2 (hi+lo), K/V single. Q pre-scaled by 1/sqrt(HD).
__device__ __align__(16) __half g_qh[MTOT * HD];
__device__ __align__(16) __half g_ql[MTOT * HD];
__device__ __align__(16) __half g_kh[MTOT * HD];
__device__ __align__(16) __half g_vh[MTOT * HD];

__device__ __forceinline__ uint32_t smem_u32(const void* p) {
  return (uint32_t)__cvta_generic_to_shared(p);
}

__device__ __forceinline__ void mma_bf16(float* d, const uint32_t* a,
                                         const uint32_t* b) {
  asm volatile(
      "mma.sync.aligned.m16n8k16.row.col.f32.bf16.bf16.f32 "
      "{%0,%1,%2,%3}, {%4,%5,%6,%7}, {%8,%9}, {%0,%1,%2,%3};\n"
      : "+f"(d[0]), "+f"(d[1]), "+f"(d[2]), "+f"(d[3])
      : "r"(a[0]), "r"(a[1]), "r"(a[2]), "r"(a[3]), "r"(b[0]), "r"(b[1]));
}
__device__ __forceinline__ void mma_fp16(float* d, const uint32_t* a,
                                         const uint32_t* b) {
  asm volatile(
      "mma.sync.aligned.m16n8k16.row.col.f32.f16.f16.f32 "
      "{%0,%1,%2,%3}, {%4,%5,%6,%7}, {%8,%9}, {%0,%1,%2,%3};\n"
      : "+f"(d[0]), "+f"(d[1]), "+f"(d[2]), "+f"(d[3])
      : "r"(a[0]), "r"(a[1]), "r"(a[2]), "r"(a[3]), "r"(b[0]), "r"(b[1]));
}

__device__ __forceinline__ void ldm_x4(uint32_t* r, uint32_t addr) {
  asm volatile(
      "ldmatrix.sync.aligned.m8n8.x4.shared.b16 {%0,%1,%2,%3}, [%4];"
      : "=r"(r[0]), "=r"(r[1]), "=r"(r[2]), "=r"(r[3]) : "r"(addr));
}
__device__ __forceinline__ void ldm_x4_t(uint32_t* r, uint32_t addr) {
  asm volatile(
      "ldmatrix.sync.aligned.m8n8.x4.trans.shared.b16 {%0,%1,%2,%3}, [%4];"
      : "=r"(r[0]), "=r"(r[1]), "=r"(r[2]), "=r"(r[3]) : "r"(addr));
}

#define CP16(dst, src) \
  asm volatile("cp.async.cg.shared.global [%0], [%1], 16;" :: "r"(dst), "l"(src))
#define CP_COMMIT() asm volatile("cp.async.commit_group;" ::: "memory")
#define CP_WAIT0() asm volatile("cp.async.wait_group 0;" ::: "memory")
#define CP_WAIT1() asm volatile("cp.async.wait_group 1;" ::: "memory")

// 8 fp32 -> 8 bf16 hi + 8 bf16 lo
__device__ __forceinline__ void cvt8(float4 a0, float4 a1, uint4& hi, uint4& lo) {
  __nv_bfloat162 h0 = __floats2bfloat162_rn(a0.x, a0.y);
  __nv_bfloat162 h1 = __floats2bfloat162_rn(a0.z, a0.w);
  __nv_bfloat162 h2 = __floats2bfloat162_rn(a1.x, a1.y);
  __nv_bfloat162 h3 = __floats2bfloat162_rn(a1.z, a1.w);
  __nv_bfloat162 l0 = __floats2bfloat162_rn(a0.x - __bfloat162float(h0.x),
                                            a0.y - __bfloat162float(h0.y));
  __nv_bfloat162 l1 = __floats2bfloat162_rn(a0.z - __bfloat162float(h1.x),
                                            a0.w - __bfloat162float(h1.y));
  __nv_bfloat162 l2 = __floats2bfloat162_rn(a1.x - __bfloat162float(h2.x),
                                            a1.y - __bfloat162float(h2.y));
  __nv_bfloat162 l3 = __floats2bfloat162_rn(a1.z - __bfloat162float(h3.x),
                                            a1.w - __bfloat162float(h3.y));
  hi = make_uint4(*(uint32_t*)&h0, *(uint32_t*)&h1, *(uint32_t*)&h2, *(uint32_t*)&h3);
  lo = make_uint4(*(uint32_t*)&l0, *(uint32_t*)&l1, *(uint32_t*)&l2, *(uint32_t*)&l3);
}

// ---------------------------------------------------------------------------
// Kernel 1: QKV projection (bf16 HMMA split-3 internally; fp16 outputs).
// ---------------------------------------------------------------------------
#define RSTRIDE 80
#define TILE_B (128 * RSTRIDE)
#define BUF_B (4 * TILE_B)

__global__ __launch_bounds__(512) void qkv_hmma(
    const float* __restrict__ x, const float* __restrict__ Wq,
    const float* __restrict__ Wk, const float* __restrict__ Wv) {
  extern __shared__ __align__(1024) char smem[];
  const float* W = (blockIdx.y == 0) ? Wq : (blockIdx.y == 1 ? Wk : Wv);

  const int tid = threadIdx.x;
  const int lane = tid & 31, wid = tid >> 5;
  const int wm = wid >> 2, wn = wid & 3;
  const int m0 = blockIdx.x * 128;
  const uint32_t sb = smem_u32(smem);

  const int lrow = tid >> 2, lc = tid & 3;
  const float* aSrc = x + (size_t)(m0 + lrow) * DM + lc * 8;
  const float* bSrc = W + (size_t)lrow * DM + lc * 8;
  const uint32_t stoOff = lrow * RSTRIDE + lc * 16;

  const int lane15 = lane & 15;
  const uint32_t aColOff = (lane >> 4) * 16;
  const uint32_t aRowB = (wm * 32 + lane15) * RSTRIDE;
  const uint32_t bRowB = (wn * 32 + ((lane >> 4) << 3) + (lane & 7)) * RSTRIDE;
  const uint32_t bColOff = ((lane >> 3) & 1) * 16;

  float acc[2][4][4];
#pragma unroll
  for (int i = 0; i < 2; i++)
#pragma unroll
    for (int j = 0; j < 4; j++)
#pragma unroll
      for (int r = 0; r < 4; r++) acc[i][j][r] = 0.f;

  float4 pA0, pA1, pB0, pB1;
  pA0 = *(const float4*)(aSrc);
  pA1 = *(const float4*)(aSrc + 4);
  pB0 = *(const float4*)(bSrc);
  pB1 = *(const float4*)(bSrc + 4);
  {
    uint4 hi, lo;
    char* p = smem + stoOff;
    cvt8(pA0, pA1, hi, lo);
    *(uint4*)(p) = hi;
    *(uint4*)(p + TILE_B) = lo;
    cvt8(pB0, pB1, hi, lo);
    *(uint4*)(p + 2 * TILE_B) = hi;
    *(uint4*)(p + 3 * TILE_B) = lo;
  }
  __syncthreads();

  for (int kt = 0; kt < 32; kt++) {
    if (kt < 31) {
      const float* a = aSrc + (kt + 1) * 32;
      const float* b = bSrc + (kt + 1) * 32;
      pA0 = *(const float4*)(a);
      pA1 = *(const float4*)(a + 4);
      pB0 = *(const float4*)(b);
      pB1 = *(const float4*)(b + 4);
    }
    const uint32_t bufBase = sb + (kt & 1) * BUF_B;
#pragma unroll
    for (int s = 0; s < 2; s++) {
      uint32_t ah[2][4], al[2][4], bh[2][4], bl[2][4];
#pragma unroll
      for (int i = 0; i < 2; i++) {
        uint32_t aa = bufBase + aRowB + i * (16 * RSTRIDE) + s * 32 + aColOff;
        ldm_x4(ah[i], aa);
        ldm_x4(al[i], aa + TILE_B);
      }
#pragma unroll
      for (int j = 0; j < 2; j++) {
        uint32_t ba = bufBase + 2 * TILE_B + bRowB + j * (16 * RSTRIDE) + s * 32 + bColOff;
        ldm_x4(bh[j], ba);
        ldm_x4(bl[j], ba + TILE_B);
      }
#pragma unroll
      for (int i = 0; i < 2; i++)
#pragma unroll
        for (int jj = 0; jj < 4; jj++) {
          const uint32_t* bhp = &bh[jj >> 1][(jj & 1) * 2];
          const uint32_t* blp = &bl[jj >> 1][(jj & 1) * 2];
          mma_bf16(acc[i][jj], ah[i], bhp);
          mma_bf16(acc[i][jj], ah[i], blp);
          mma_bf16(acc[i][jj], al[i], bhp);
        }
    }
    if (kt < 31) {
      char* p = smem + ((kt + 1) & 1) * BUF_B + stoOff;
      uint4 hi, lo;
      cvt8(pA0, pA1, hi, lo);
      *(uint4*)(p) = hi;
      *(uint4*)(p + TILE_B) = lo;
      cvt8(pB0, pB1, hi, lo);
      *(uint4*)(p + 2 * TILE_B) = hi;
      *(uint4*)(p + 3 * TILE_B) = lo;
    }
    __syncthreads();
  }

  const int g = lane >> 2, tig = lane & 3;
  const int yid = blockIdx.y;
  const float qs = (yid == 0) ? 0.08838834764831845f : 1.0f;
  __half* oh = (yid == 0) ? g_qh : (yid == 1 ? g_kh : g_vh);
#pragma unroll
  for (int i = 0; i < 2; i++) {
    int r0 = m0 + wm * 32 + i * 16 + g;
#pragma unroll
    for (int jj = 0; jj < 4; jj++) {
      int col = wn * 32 + jj * 8 + 2 * tig;
      float v0 = acc[i][jj][0] * qs, v1 = acc[i][jj][1] * qs;
      float v2 = acc[i][jj][2] * qs, v3 = acc[i][jj][3] * qs;
      __half2 h01 = __floats2half2_rn(v0, v1);
      __half2 h23 = __floats2half2_rn(v2, v3);
      *(uint32_t*)&oh[(size_t)r0 * HD + col] = *(uint32_t*)&h01;
      *(uint32_t*)&oh[(size_t)(r0 + 8) * HD + col] = *(uint32_t*)&h23;
      if (yid == 0) {
        __half2 l01 = __floats2half2_rn(v0 - __low2float(h01), v1 - __high2float(h01));
        __half2 l23 = __floats2half2_rn(v2 - __low2float(h23), v3 - __high2float(h23));
        *(uint32_t*)&g_ql[(size_t)r0 * HD + col] = *(uint32_t*)&l01;
        *(uint32_t*)&g_ql[(size_t)(r0 + 8) * HD + col] = *(uint32_t*)&l23;
      }
    }
  }
}

// ---------------------------------------------------------------------------
// Kernel 2: causal flash attention, fp16 HMMA, 4 MMAs/tile-pair:
//   S = (Qh+Ql)K,  O += (Ph+Pl)V.  512 thr = 16 warps, warp grid 4m x 4n.
// cp.async double-buffered KV. Paired q-tiles: 33 iters/CTA, grid (16,8).
// ---------------------------------------------------------------------------
#define QSTR 272   // 128 fp16 cols * 2B + 16 pad
#define PSTR 144   // 64 fp16 cols * 2B + 16 pad
#define KVB_K 17408
#define KVSTG 34816          // K + V per stage
#define OFF_KV 34816         // after Qh/Ql region
#define OFF_P (OFF_KV + 2 * KVSTG)   // 104448
#define OFF_PL (OFF_P + 9216)        // 113664
#define OFF_MS (OFF_P + 18432)       // 122880
#define ATT_SMEM (OFF_MS + 1024)     // 123904

__global__ __launch_bounds__(512) void attn_mma(float* __restrict__ out) {
  extern __shared__ __align__(16) char smA[];
  const uint32_t sb = smem_u32(smA);
  float* msm = (float*)(smA + OFF_MS);  // [64][4]

  const int tid = threadIdx.x, lane = tid & 31, wid = tid >> 5;
  const int wm = wid & 3, wn = wid >> 2;
  const int g = lane >> 2, tig = lane & 3;
  const int b = blockIdx.y;

  const int aRow = lane & 15;
  const int aCol = (lane >> 4) * 16;
  const int bRow = ((lane >> 4) << 3) + (lane & 7);
  const int bCol = ((lane >> 3) & 1) * 16;
  const int vRow = (lane & 7) + (((lane >> 3) & 1) << 3);
  const int vCol = (lane >> 4) * 8;
  const int rA = 16 * wm + g;

  // cp.async role: row = tid>>3 (0..63), 16B chunk c and c+8
  const int ldRow = tid >> 3, ldC = tid & 7;
  const uint32_t ldDst = ldRow * QSTR + ldC * 16;
  const size_t ldSrc = (size_t)ldRow * HD + ldC * 8;

  for (int phse = 0; phse < 2; phse++) {
    const int qt = phse ? (31 - blockIdx.x) : blockIdx.x;
    const size_t qoff = ((size_t)b * TSEQ + (size_t)qt * 64) * HD;
    __syncthreads();  // prev phase fully done
    // ---- stage Q (hi/lo) into dedicated region ----
    {
      const uint4* qhp = (const uint4*)(g_qh + qoff);
      const uint4* qlp = (const uint4*)(g_ql + qoff);
#pragma unroll
      for (int it = 0; it < 2; it++) {
        int idx = tid + it * 512;
        uint32_t d = (idx >> 4) * QSTR + (idx & 15) * 16;
        *(uint4*)(smA + d) = qhp[idx];
        *(uint4*)(smA + KVB_K + d) = qlp[idx];
      }
    }
    // ---- prologue: cp.async KV tile 0 into buffer 0 ----
    {
      const size_t koff = (size_t)b * TSEQ * HD;
      const uint32_t d0 = sb + OFF_KV + ldDst;
      CP16(d0, g_kh + koff + ldSrc);
      CP16(d0 + 128, g_kh + koff + ldSrc + 64);
      CP16(d0 + KVB_K, g_vh + koff + ldSrc);
      CP16(d0 + KVB_K + 128, g_vh + koff + ldSrc + 64);
      CP_COMMIT();
    }

    float O[4][4];
#pragma unroll
    for (int nt = 0; nt < 4; nt++)
#pragma unroll
      for (int r = 0; r < 4; r++) O[nt][r] = 0.f;
    float m_r[2] = {-1e30f, -1e30f}, l_r[2] = {0.f, 0.f};

    for (int kb = 0; kb <= qt; kb++) {
      const uint32_t kvb = sb + OFF_KV + (kb & 1) * KVSTG;
      if (kb < qt) {
        const size_t koff = ((size_t)b * TSEQ + (size_t)(kb + 1) * 64) * HD;
        const uint32_t ob = sb + OFF_KV + ((kb + 1) & 1) * KVSTG + ldDst;
        CP16(ob, g_kh + koff + ldSrc);
        CP16(ob + 128, g_kh + koff + ldSrc + 64);
        CP16(ob + KVB_K, g_vh + koff + ldSrc);
        CP16(ob + KVB_K + 128, g_vh + koff + ldSrc + 64);
        CP_COMMIT();
        CP_WAIT1();
      } else {
        CP_WAIT0();
      }
      __syncthreads();  // (1) KV + (first iter) Q staging visible

      // ---- S = (Qh + Ql) K ----
      float sfr[2][4];
#pragma unroll
      for (int nt = 0; nt < 2; nt++)
#pragma unroll
        for (int r = 0; r < 4; r++) sfr[nt][r] = 0.f;
#pragma unroll
      for (int c = 0; c < 8; c++) {
        uint32_t qh4[4], ql4[4], kh4[4];
        uint32_t qa = sb + (16 * wm + aRow) * QSTR + c * 32 + aCol;
        ldm_x4(qh4, qa);
        ldm_x4(ql4, qa + KVB_K);
        ldm_x4(kh4, kvb + (16 * wn + bRow) * QSTR + c * 32 + bCol);
#pragma unroll
        for (int h = 0; h < 2; h++) {
          mma_fp16(sfr[h], qh4, &kh4[2 * h]);
          mma_fp16(sfr[h], ql4, &kh4[2 * h]);
        }
      }

      if (kb == qt) {
#pragma unroll
        for (int nt = 0; nt < 2; nt++) {
          int colRel = 16 * wn + 8 * nt + 2 * tig;
          if (colRel > rA) sfr[nt][0] = -1e30f;
          if (colRel + 1 > rA) sfr[nt][1] = -1e30f;
          if (colRel > rA + 8) sfr[nt][2] = -1e30f;
          if (colRel + 1 > rA + 8) sfr[nt][3] = -1e30f;
        }
      }

      // ---- row maxes: quad reduce + 4-way cross-warp via smem ----
      float mxA = fmaxf(fmaxf(sfr[0][0], sfr[0][1]), fmaxf(sfr[1][0], sfr[1][1]));
      float mxB = fmaxf(fmaxf(sfr[0][2], sfr[0][3]), fmaxf(sfr[1][2], sfr[1][3]));
#pragma unroll
      for (int o = 1; o <= 2; o <<= 1) {
        mxA = fmaxf(mxA, __shfl_xor_sync(0xffffffffu, mxA, o));
        mxB = fmaxf(mxB, __shfl_xor_sync(0xffffffffu, mxB, o));
      }
      if (tig == 0) {
        msm[rA * 4 + wn] = mxA;
        msm[(rA + 8) * 4 + wn] = mxB;
      }
      __syncthreads();  // (2)
      float nmA = fmaxf(m_r[0],
                        fmaxf(fmaxf(msm[rA * 4 + 0], msm[rA * 4 + 1]),
                              fmaxf(msm[rA * 4 + 2], msm[rA * 4 + 3])));
      float nmB = fmaxf(m_r[1],
                        fmaxf(fmaxf(msm[(rA + 8) * 4 + 0], msm[(rA + 8) * 4 + 1]),
                              fmaxf(msm[(rA + 8) * 4 + 2], msm[(rA + 8) * 4 + 3])));
      float corrA = __expf(m_r[0] - nmA);
      float corrB = __expf(m_r[1] - nmB);
      m_r[0] = nmA;
      m_r[1] = nmB;

      float sumA = 0.f, sumB = 0.f;
#pragma unroll
      for (int nt = 0; nt < 2; nt++) {
        float pa0 = __expf(sfr[nt][0] - nmA), pa1 = __expf(sfr[nt][1] - nmA);
        float pb0 = __expf(sfr[nt][2] - nmB), pb1 = __expf(sfr[nt][3] - nmB);
        sumA += pa0 + pa1;
        sumB += pb0 + pb1;
        int colb = (16 * wn + 8 * nt + 2 * tig) * 2;
        __half2 ha = __floats2half2_rn(pa0, pa1);
        __half2 la = __floats2half2_rn(pa0 - __low2float(ha), pa1 - __high2float(ha));
        __half2 hb = __floats2half2_rn(pb0, pb1);
        __half2 lb = __floats2half2_rn(pb0 - __low2float(hb), pb1 - __high2float(hb));
        *(uint32_t*)(smA + OFF_P + rA * PSTR + colb) = *(uint32_t*)&ha;
        *(uint32_t*)(smA + OFF_PL + rA * PSTR + colb) = *(uint32_t*)&la;
        *(uint32_t*)(smA + OFF_P + (rA + 8) * PSTR + colb) = *(uint32_t*)&hb;
        *(uint32_t*)(smA + OFF_PL + (rA + 8) * PSTR + colb) = *(uint32_t*)&lb;
      }
#pragma unroll
      for (int o = 1; o <= 2; o <<= 1) {
        sumA += __shfl_xor_sync(0xffffffffu, sumA, o);
        sumB += __shfl_xor_sync(0xffffffffu, sumB, o);
      }
      l_r[0] = l_r[0] * corrA + sumA;  // partial over this warp's 16 cols
      l_r[1] = l_r[1] * corrB + sumB;
#pragma unroll
      for (int nt = 0; nt < 4; nt++) {
        O[nt][0] *= corrA;
        O[nt][1] *= corrA;
        O[nt][2] *= corrB;
        O[nt][3] *= corrB;
      }
      __syncthreads();  // (3) P visible

      // ---- O += (Ph + Pl) V ----
#pragma unroll
      for (int ck = 0; ck < 4; ck++) {
        uint32_t pfh[4], pfl[4];
        uint32_t ad = sb + OFF_P + (16 * wm + aRow) * PSTR + ck * 32 + aCol;
        ldm_x4(pfh, ad);
        ldm_x4(pfl, ad + 9216);
#pragma unroll
        for (int pv = 0; pv < 2; pv++) {
          uint32_t vh4[4];
          uint32_t vd = kvb + KVB_K + (16 * ck + vRow) * QSTR +
                        (32 * wn + 16 * pv + vCol) * 2;
          ldm_x4_t(vh4, vd);
#pragma unroll
          for (int h = 0; h < 2; h++) {
            int nt = 2 * pv + h;
            mma_fp16(O[nt], pfh, &vh4[2 * h]);
            mma_fp16(O[nt], pfl, &vh4[2 * h]);
          }
        }
      }
      __syncthreads();  // (4) V/P reads done before next overwrite
    }

    // ---- epilogue: merge per-warp l partials, normalize, write ----
    if (tig == 0) {
      msm[rA * 4 + wn] = l_r[0];
      msm[(rA + 8) * 4 + wn] = l_r[1];
    }
    __syncthreads();
    float liA = 1.f / (msm[rA * 4 + 0] + msm[rA * 4 + 1] + msm[rA * 4 + 2] +
                       msm[rA * 4 + 3]);
    float liB = 1.f / (msm[(rA + 8) * 4 + 0] + msm[(rA + 8) * 4 + 1] +
                       msm[(rA + 8) * 4 + 2] + msm[(rA + 8) * 4 + 3]);
    const size_t tA = (size_t)b * TSEQ + qt * 64 + rA;
#pragma unroll
    for (int nt = 0; nt < 4; nt++) {
      int col = 32 * wn + 8 * nt + 2 * tig;
      *(float2*)&out[tA * HD + col] = make_float2(O[nt][0] * liA, O[nt][1] * liA);
      *(float2*)&out[(tA + 8) * HD + col] =
          make_float2(O[nt][2] * liB, O[nt][3] * liB);
    }
  }
}

extern "C" void kernel_launch(void* const* d_in, const int* in_sizes, int n_in,
                              void* d_out, int out_size) {
  (void)in_sizes; (void)n_in; (void)out_size;
  const float* x  = (const float*)d_in[0];
  const float* Wq = (const float*)d_in[1];
  const float* Wk = (const float*)d_in[2];
  const float* Wv = (const float*)d_in[3];
  float* out = (float*)d_out;

  const int SMEMQ = 2 * BUF_B;  // 81920 B
  cudaFuncSetAttribute(qkv_hmma, cudaFuncAttributeMaxDynamicSharedMemorySize,
                       SMEMQ);
  dim3 g1(128, 3);
  qkv_hmma<<<g1, 512, SMEMQ>>>(x, Wq, Wk, Wv);

  cudaFuncSetAttribute(attn_mma, cudaFuncAttributeMaxDynamicSharedMemorySize,
                       ATT_SMEM);
  dim3 g2(16, 8);
  attn_mma<<<g2, 512, ATT_SMEM>>>(out);
}

// round 8
// speedup vs baseline: 4.5312x; 1.1783x over previous
#include <cuda_runtime.h>
#include <cuda_fp16.h>
#include <cstdint>

#define TSEQ 2048
#define BATCH 8
#define DM 1024
#define HD 128
#define MTOT (BATCH * TSEQ)

// fp16 scratch: Q split-2 (hi+lo), K/V single. Q pre-scaled by 1/sqrt(HD).
__device__ __align__(16) __half g_qh[MTOT * HD];
__device__ __align__(16) __half g_ql[MTOT * HD];
__device__ __align__(16) __half g_kh[MTOT * HD];
__device__ __align__(16) __half g_vh[MTOT * HD];

__device__ __forceinline__ uint32_t smem_u32(const void* p) {
  return (uint32_t)__cvta_generic_to_shared(p);
}

__device__ __forceinline__ void mma_fp16(float* d, const uint32_t* a,
                                         const uint32_t* b) {
  asm volatile(
      "mma.sync.aligned.m16n8k16.row.col.f32.f16.f16.f32 "
      "{%0,%1,%2,%3}, {%4,%5,%6,%7}, {%8,%9}, {%0,%1,%2,%3};\n"
      : "+f"(d[0]), "+f"(d[1]), "+f"(d[2]), "+f"(d[3])
      : "r"(a[0]), "r"(a[1]), "r"(a[2]), "r"(a[3]), "r"(b[0]), "r"(b[1]));
}

__device__ __forceinline__ void ldm_x4(uint32_t* r, uint32_t addr) {
  asm volatile(
      "ldmatrix.sync.aligned.m8n8.x4.shared.b16 {%0,%1,%2,%3}, [%4];"
      : "=r"(r[0]), "=r"(r[1]), "=r"(r[2]), "=r"(r[3]) : "r"(addr));
}
__device__ __forceinline__ void ldm_x4_t(uint32_t* r, uint32_t addr) {
  asm volatile(
      "ldmatrix.sync.aligned.m8n8.x4.trans.shared.b16 {%0,%1,%2,%3}, [%4];"
      : "=r"(r[0]), "=r"(r[1]), "=r"(r[2]), "=r"(r[3]) : "r"(addr));
}

#define CP16(dst, src) \
  asm volatile("cp.async.cg.shared.global [%0], [%1], 16;" :: "r"(dst), "l"(src))
#define CP_COMMIT() asm volatile("cp.async.commit_group;" ::: "memory")
#define CP_WAIT0() asm volatile("cp.async.wait_group 0;" ::: "memory")
#define CP_WAIT1() asm volatile("cp.async.wait_group 1;" ::: "memory")

// 8 fp32 -> 8 fp16 hi + 8 fp16 lo
__device__ __forceinline__ void cvt8h(float4 a0, float4 a1, uint4& hi, uint4& lo) {
  __half2 h0 = __floats2half2_rn(a0.x, a0.y);
  __half2 h1 = __floats2half2_rn(a0.z, a0.w);
  __half2 h2 = __floats2half2_rn(a1.x, a1.y);
  __half2 h3 = __floats2half2_rn(a1.z, a1.w);
  __half2 l0 = __floats2half2_rn(a0.x - __low2float(h0), a0.y - __high2float(h0));
  __half2 l1 = __floats2half2_rn(a0.z - __low2float(h1), a0.w - __high2float(h1));
  __half2 l2 = __floats2half2_rn(a1.x - __low2float(h2), a1.y - __high2float(h2));
  __half2 l3 = __floats2half2_rn(a1.z - __low2float(h3), a1.w - __high2float(h3));
  hi = make_uint4(*(uint32_t*)&h0, *(uint32_t*)&h1, *(uint32_t*)&h2, *(uint32_t*)&h3);
  lo = make_uint4(*(uint32_t*)&l0, *(uint32_t*)&l1, *(uint32_t*)&l2, *(uint32_t*)&l3);
}
// 8 fp32 -> 8 fp16 (single)
__device__ __forceinline__ uint4 cvt8s(float4 a0, float4 a1) {
  __half2 h0 = __floats2half2_rn(a0.x, a0.y);
  __half2 h1 = __floats2half2_rn(a0.z, a0.w);
  __half2 h2 = __floats2half2_rn(a1.x, a1.y);
  __half2 h3 = __floats2half2_rn(a1.z, a1.w);
  return make_uint4(*(uint32_t*)&h0, *(uint32_t*)&h1, *(uint32_t*)&h2,
                    *(uint32_t*)&h3);
}

// ---------------------------------------------------------------------------
// Kernel 1: QKV projection, fp16 HMMA, asymmetric split-2:
//   y = (xh + xl) * W_fp16.  2 MMAs per product. BK=32, double-buffered,
//   80B row stride. 512 threads, warp grid 4x4, warp tile 32x32.
// ---------------------------------------------------------------------------
#define RSTRIDE 80
#define TILE_B (128 * RSTRIDE)  // 10240
#define NBUF_B (3 * TILE_B)     // Xh, Xl, W

__global__ __launch_bounds__(512) void qkv_hmma(
    const float* __restrict__ x, const float* __restrict__ Wq,
    const float* __restrict__ Wk, const float* __restrict__ Wv) {
  extern __shared__ __align__(1024) char smem[];
  const float* W = (blockIdx.y == 0) ? Wq : (blockIdx.y == 1 ? Wk : Wv);

  const int tid = threadIdx.x;
  const int lane = tid & 31, wid = tid >> 5;
  const int wm = wid >> 2, wn = wid & 3;
  const int m0 = blockIdx.x * 128;
  const uint32_t sb = smem_u32(smem);

  const int lrow = tid >> 2, lc = tid & 3;
  const float* aSrc = x + (size_t)(m0 + lrow) * DM + lc * 8;
  const float* bSrc = W + (size_t)lrow * DM + lc * 8;
  const uint32_t stoOff = lrow * RSTRIDE + lc * 16;

  const int lane15 = lane & 15;
  const uint32_t aColOff = (lane >> 4) * 16;
  const uint32_t aRowB = (wm * 32 + lane15) * RSTRIDE;
  const uint32_t bRowB = (wn * 32 + ((lane >> 4) << 3) + (lane & 7)) * RSTRIDE;
  const uint32_t bColOff = ((lane >> 3) & 1) * 16;

  float acc[2][4][4];
#pragma unroll
  for (int i = 0; i < 2; i++)
#pragma unroll
    for (int j = 0; j < 4; j++)
#pragma unroll
      for (int r = 0; r < 4; r++) acc[i][j][r] = 0.f;

  float4 pA0, pA1, pB0, pB1;
  pA0 = *(const float4*)(aSrc);
  pA1 = *(const float4*)(aSrc + 4);
  pB0 = *(const float4*)(bSrc);
  pB1 = *(const float4*)(bSrc + 4);
  {
    uint4 hi, lo;
    char* p = smem + stoOff;
    cvt8h(pA0, pA1, hi, lo);
    *(uint4*)(p) = hi;
    *(uint4*)(p + TILE_B) = lo;
    *(uint4*)(p + 2 * TILE_B) = cvt8s(pB0, pB1);
  }
  __syncthreads();

  for (int kt = 0; kt < 32; kt++) {
    if (kt < 31) {
      const float* a = aSrc + (kt + 1) * 32;
      const float* b = bSrc + (kt + 1) * 32;
      pA0 = *(const float4*)(a);
      pA1 = *(const float4*)(a + 4);
      pB0 = *(const float4*)(b);
      pB1 = *(const float4*)(b + 4);
    }
    const uint32_t bufBase = sb + (kt & 1) * NBUF_B;
#pragma unroll
    for (int s = 0; s < 2; s++) {
      uint32_t ah[2][4], al[2][4], b2[2][4];
#pragma unroll
      for (int i = 0; i < 2; i++) {
        uint32_t aa = bufBase + aRowB + i * (16 * RSTRIDE) + s * 32 + aColOff;
        ldm_x4(ah[i], aa);
        ldm_x4(al[i], aa + TILE_B);
      }
#pragma unroll
      for (int j = 0; j < 2; j++) {
        uint32_t ba = bufBase + 2 * TILE_B + bRowB + j * (16 * RSTRIDE) + s * 32 + bColOff;
        ldm_x4(b2[j], ba);
      }
#pragma unroll
      for (int i = 0; i < 2; i++)
#pragma unroll
        for (int jj = 0; jj < 4; jj++) {
          const uint32_t* bp = &b2[jj >> 1][(jj & 1) * 2];
          mma_fp16(acc[i][jj], ah[i], bp);
          mma_fp16(acc[i][jj], al[i], bp);
        }
    }
    if (kt < 31) {
      char* p = smem + ((kt + 1) & 1) * NBUF_B + stoOff;
      uint4 hi, lo;
      cvt8h(pA0, pA1, hi, lo);
      *(uint4*)(p) = hi;
      *(uint4*)(p + TILE_B) = lo;
      *(uint4*)(p + 2 * TILE_B) = cvt8s(pB0, pB1);
    }
    __syncthreads();
  }

  const int g = lane >> 2, tig = lane & 3;
  const int yid = blockIdx.y;
  const float qs = (yid == 0) ? 0.08838834764831845f : 1.0f;
  __half* oh = (yid == 0) ? g_qh : (yid == 1 ? g_kh : g_vh);
#pragma unroll
  for (int i = 0; i < 2; i++) {
    int r0 = m0 + wm * 32 + i * 16 + g;
#pragma unroll
    for (int jj = 0; jj < 4; jj++) {
      int col = wn * 32 + jj * 8 + 2 * tig;
      float v0 = acc[i][jj][0] * qs, v1 = acc[i][jj][1] * qs;
      float v2 = acc[i][jj][2] * qs, v3 = acc[i][jj][3] * qs;
      __half2 h01 = __floats2half2_rn(v0, v1);
      __half2 h23 = __floats2half2_rn(v2, v3);
      *(uint32_t*)&oh[(size_t)r0 * HD + col] = *(uint32_t*)&h01;
      *(uint32_t*)&oh[(size_t)(r0 + 8) * HD + col] = *(uint32_t*)&h23;
      if (yid == 0) {
        __half2 l01 = __floats2half2_rn(v0 - __low2float(h01), v1 - __high2float(h01));
        __half2 l23 = __floats2half2_rn(v2 - __low2float(h23), v3 - __high2float(h23));
        *(uint32_t*)&g_ql[(size_t)r0 * HD + col] = *(uint32_t*)&l01;
        *(uint32_t*)&g_ql[(size_t)(r0 + 8) * HD + col] = *(uint32_t*)&l23;
      }
    }
  }
}

// ---------------------------------------------------------------------------
// Kernel 2: causal flash attention, fp16 HMMA, 4 MMAs/tile-pair (unchanged,
// known-good 84.9us). 512 thr, cp.async double-buffered KV, paired q-tiles.
// ---------------------------------------------------------------------------
#define QSTR 272
#define PSTR 144
#define KVB_K 17408
#define KVSTG 34816
#define OFF_KV 34816
#define OFF_P (OFF_KV + 2 * KVSTG)
#define OFF_PL (OFF_P + 9216)
#define OFF_MS (OFF_P + 18432)
#define ATT_SMEM (OFF_MS + 1024)

__global__ __launch_bounds__(512) void attn_mma(float* __restrict__ out) {
  extern __shared__ __align__(16) char smA[];
  const uint32_t sb = smem_u32(smA);
  float* msm = (float*)(smA + OFF_MS);

  const int tid = threadIdx.x, lane = tid & 31, wid = tid >> 5;
  const int wm = wid & 3, wn = wid >> 2;
  const int g = lane >> 2, tig = lane & 3;
  const int b = blockIdx.y;

  const int aRow = lane & 15;
  const int aCol = (lane >> 4) * 16;
  const int bRow = ((lane >> 4) << 3) + (lane & 7);
  const int bCol = ((lane >> 3) & 1) * 16;
  const int vRow = (lane & 7) + (((lane >> 3) & 1) << 3);
  const int vCol = (lane >> 4) * 8;
  const int rA = 16 * wm + g;

  const int ldRow = tid >> 3, ldC = tid & 7;
  const uint32_t ldDst = ldRow * QSTR + ldC * 16;
  const size_t ldSrc = (size_t)ldRow * HD + ldC * 8;

  for (int phse = 0; phse < 2; phse++) {
    const int qt = phse ? (31 - blockIdx.x) : blockIdx.x;
    const size_t qoff = ((size_t)b * TSEQ + (size_t)qt * 64) * HD;
    __syncthreads();
    {
      const uint4* qhp = (const uint4*)(g_qh + qoff);
      const uint4* qlp = (const uint4*)(g_ql + qoff);
#pragma unroll
      for (int it = 0; it < 2; it++) {
        int idx = tid + it * 512;
        uint32_t d = (idx >> 4) * QSTR + (idx & 15) * 16;
        *(uint4*)(smA + d) = qhp[idx];
        *(uint4*)(smA + KVB_K + d) = qlp[idx];
      }
    }
    {
      const size_t koff = (size_t)b * TSEQ * HD;
      const uint32_t d0 = sb + OFF_KV + ldDst;
      CP16(d0, g_kh + koff + ldSrc);
      CP16(d0 + 128, g_kh + koff + ldSrc + 64);
      CP16(d0 + KVB_K, g_vh + koff + ldSrc);
      CP16(d0 + KVB_K + 128, g_vh + koff + ldSrc + 64);
      CP_COMMIT();
    }

    float O[4][4];
#pragma unroll
    for (int nt = 0; nt < 4; nt++)
#pragma unroll
      for (int r = 0; r < 4; r++) O[nt][r] = 0.f;
    float m_r[2] = {-1e30f, -1e30f}, l_r[2] = {0.f, 0.f};

    for (int kb = 0; kb <= qt; kb++) {
      const uint32_t kvb = sb + OFF_KV + (kb & 1) * KVSTG;
      if (kb < qt) {
        const size_t koff = ((size_t)b * TSEQ + (size_t)(kb + 1) * 64) * HD;
        const uint32_t ob = sb + OFF_KV + ((kb + 1) & 1) * KVSTG + ldDst;
        CP16(ob, g_kh + koff + ldSrc);
        CP16(ob + 128, g_kh + koff + ldSrc + 64);
        CP16(ob + KVB_K, g_vh + koff + ldSrc);
        CP16(ob + KVB_K + 128, g_vh + koff + ldSrc + 64);
        CP_COMMIT();
        CP_WAIT1();
      } else {
        CP_WAIT0();
      }
      __syncthreads();

      float sfr[2][4];
#pragma unroll
      for (int nt = 0; nt < 2; nt++)
#pragma unroll
        for (int r = 0; r < 4; r++) sfr[nt][r] = 0.f;
#pragma unroll
      for (int c = 0; c < 8; c++) {
        uint32_t qh4[4], ql4[4], kh4[4];
        uint32_t qa = sb + (16 * wm + aRow) * QSTR + c * 32 + aCol;
        ldm_x4(qh4, qa);
        ldm_x4(ql4, qa + KVB_K);
        ldm_x4(kh4, kvb + (16 * wn + bRow) * QSTR + c * 32 + bCol);
#pragma unroll
        for (int h = 0; h < 2; h++) {
          mma_fp16(sfr[h], qh4, &kh4[2 * h]);
          mma_fp16(sfr[h], ql4, &kh4[2 * h]);
        }
      }

      if (kb == qt) {
#pragma unroll
        for (int nt = 0; nt < 2; nt++) {
          int colRel = 16 * wn + 8 * nt + 2 * tig;
          if (colRel > rA) sfr[nt][0] = -1e30f;
          if (colRel + 1 > rA) sfr[nt][1] = -1e30f;
          if (colRel > rA + 8) sfr[nt][2] = -1e30f;
          if (colRel + 1 > rA + 8) sfr[nt][3] = -1e30f;
        }
      }

      float mxA = fmaxf(fmaxf(sfr[0][0], sfr[0][1]), fmaxf(sfr[1][0], sfr[1][1]));
      float mxB = fmaxf(fmaxf(sfr[0][2], sfr[0][3]), fmaxf(sfr[1][2], sfr[1][3]));
#pragma unroll
      for (int o = 1; o <= 2; o <<= 1) {
        mxA = fmaxf(mxA, __shfl_xor_sync(0xffffffffu, mxA, o));
        mxB = fmaxf(mxB, __shfl_xor_sync(0xffffffffu, mxB, o));
      }
      if (tig == 0) {
        msm[rA * 4 + wn] = mxA;
        msm[(rA + 8) * 4 + wn] = mxB;
      }
      __syncthreads();
      float nmA = fmaxf(m_r[0],
                        fmaxf(fmaxf(msm[rA * 4 + 0], msm[rA * 4 + 1]),
                              fmaxf(msm[rA * 4 + 2], msm[rA * 4 + 3])));
      float nmB = fmaxf(m_r[1],
                        fmaxf(fmaxf(msm[(rA + 8) * 4 + 0], msm[(rA + 8) * 4 + 1]),
                              fmaxf(msm[(rA + 8) * 4 + 2], msm[(rA + 8) * 4 + 3])));
      float corrA = __expf(m_r[0] - nmA);
      float corrB = __expf(m_r[1] - nmB);
      m_r[0] = nmA;
      m_r[1] = nmB;

      float sumA = 0.f, sumB = 0.f;
#pragma unroll
      for (int nt = 0; nt < 2; nt++) {
        float pa0 = __expf(sfr[nt][0] - nmA), pa1 = __expf(sfr[nt][1] - nmA);
        float pb0 = __expf(sfr[nt][2] - nmB), pb1 = __expf(sfr[nt][3] - nmB);
        sumA += pa0 + pa1;
        sumB += pb0 + pb1;
        int colb = (16 * wn + 8 * nt + 2 * tig) * 2;
        __half2 ha = __floats2half2_rn(pa0, pa1);
        __half2 la = __floats2half2_rn(pa0 - __low2float(ha), pa1 - __high2float(ha));
        __half2 hb = __floats2half2_rn(pb0, pb1);
        __half2 lb = __floats2half2_rn(pb0 - __low2float(hb), pb1 - __high2float(hb));
        *(uint32_t*)(smA + OFF_P + rA * PSTR + colb) = *(uint32_t*)&ha;
        *(uint32_t*)(smA + OFF_PL + rA * PSTR + colb) = *(uint32_t*)&la;
        *(uint32_t*)(smA + OFF_P + (rA + 8) * PSTR + colb) = *(uint32_t*)&hb;
        *(uint32_t*)(smA + OFF_PL + (rA + 8) * PSTR + colb) = *(uint32_t*)&lb;
      }
#pragma unroll
      for (int o = 1; o <= 2; o <<= 1) {
        sumA += __shfl_xor_sync(0xffffffffu, sumA, o);
        sumB += __shfl_xor_sync(0xffffffffu, sumB, o);
      }
      l_r[0] = l_r[0] * corrA + sumA;
      l_r[1] = l_r[1] * corrB + sumB;
#pragma unroll
      for (int nt = 0; nt < 4; nt++) {
        O[nt][0] *= corrA;
        O[nt][1] *= corrA;
        O[nt][2] *= corrB;
        O[nt][3] *= corrB;
      }
      __syncthreads();

#pragma unroll
      for (int ck = 0; ck < 4; ck++) {
        uint32_t pfh[4], pfl[4];
        uint32_t ad = sb + OFF_P + (16 * wm + aRow) * PSTR + ck * 32 + aCol;
        ldm_x4(pfh, ad);
        ldm_x4(pfl, ad + 9216);
#pragma unroll
        for (int pv = 0; pv < 2; pv++) {
          uint32_t vh4[4];
          uint32_t vd = kvb + KVB_K + (16 * ck + vRow) * QSTR +
                        (32 * wn + 16 * pv + vCol) * 2;
          ldm_x4_t(vh4, vd);
#pragma unroll
          for (int h = 0; h < 2; h++) {
            int nt = 2 * pv + h;
            mma_fp16(O[nt], pfh, &vh4[2 * h]);
            mma_fp16(O[nt], pfl, &vh4[2 * h]);
          }
        }
      }
      __syncthreads();
    }

    if (tig == 0) {
      msm[rA * 4 + wn] = l_r[0];
      msm[(rA + 8) * 4 + wn] = l_r[1];
    }
    __syncthreads();
    float liA = 1.f / (msm[rA * 4 + 0] + msm[rA * 4 + 1] + msm[rA * 4 + 2] +
                       msm[rA * 4 + 3]);
    float liB = 1.f / (msm[(rA + 8) * 4 + 0] + msm[(rA + 8) * 4 + 1] +
                       msm[(rA + 8) * 4 + 2] + msm[(rA + 8) * 4 + 3]);
    const size_t tA = (size_t)b * TSEQ + qt * 64 + rA;
#pragma unroll
    for (int nt = 0; nt < 4; nt++) {
      int col = 32 * wn + 8 * nt + 2 * tig;
      *(float2*)&out[tA * HD + col] = make_float2(O[nt][0] * liA, O[nt][1] * liA);
      *(float2*)&out[(tA + 8) * HD + col] =
          make_float2(O[nt][2] * liB, O[nt][3] * liB);
    }
  }
}

extern "C" void kernel_launch(void* const* d_in, const int* in_sizes, int n_in,
                              void* d_out, int out_size) {
  (void)in_sizes; (void)n_in; (void)out_size;
  const float* x  = (const float*)d_in[0];
  const float* Wq = (const float*)d_in[1];
  const float* Wk = (const float*)d_in[2];
  const float* Wv = (const float*)d_in[3];
  float* out = (float*)d_out;

  const int SMEMQ = 2 * NBUF_B;  // 61440 B
  cudaFuncSetAttribute(qkv_hmma, cudaFuncAttributeMaxDynamicSharedMemorySize,
                       SMEMQ);
  dim3 g1(128, 3);
  qkv_hmma<<<g1, 512, SMEMQ>>>(x, Wq, Wk, Wv);

  cudaFuncSetAttribute(attn_mma, cudaFuncAttributeMaxDynamicSharedMemorySize,
                       ATT_SMEM);
  dim3 g2(16, 8);
  attn_mma<<<g2, 512, ATT_SMEM>>>(out);
}

// round 9
// speedup vs baseline: 4.6049x; 1.0163x over previous
#include <cuda_runtime.h>
#include <cuda_fp16.h>
#include <cstdint>

#define TSEQ 2048
#define BATCH 8
#define DM 1024
#define HD 128
#define MTOT (BATCH * TSEQ)

// fp16 scratch: Q split-2 (hi+lo), K/V single. Q pre-scaled by 1/sqrt(HD).
__device__ __align__(16) __half g_qh[MTOT * HD];
__device__ __align__(16) __half g_ql[MTOT * HD];
__device__ __align__(16) __half g_kh[MTOT * HD];
__device__ __align__(16) __half g_vh[MTOT * HD];

__device__ __forceinline__ uint32_t smem_u32(const void* p) {
  return (uint32_t)__cvta_generic_to_shared(p);
}

__device__ __forceinline__ void mma_fp16(float* d, const uint32_t* a,
                                         const uint32_t* b) {
  asm volatile(
      "mma.sync.aligned.m16n8k16.row.col.f32.f16.f16.f32 "
      "{%0,%1,%2,%3}, {%4,%5,%6,%7}, {%8,%9}, {%0,%1,%2,%3};\n"
      : "+f"(d[0]), "+f"(d[1]), "+f"(d[2]), "+f"(d[3])
      : "r"(a[0]), "r"(a[1]), "r"(a[2]), "r"(a[3]), "r"(b[0]), "r"(b[1]));
}

__device__ __forceinline__ void ldm_x4(uint32_t* r, uint32_t addr) {
  asm volatile(
      "ldmatrix.sync.aligned.m8n8.x4.shared.b16 {%0,%1,%2,%3}, [%4];"
      : "=r"(r[0]), "=r"(r[1]), "=r"(r[2]), "=r"(r[3]) : "r"(addr));
}
__device__ __forceinline__ void ldm_x4_t(uint32_t* r, uint32_t addr) {
  asm volatile(
      "ldmatrix.sync.aligned.m8n8.x4.trans.shared.b16 {%0,%1,%2,%3}, [%4];"
      : "=r"(r[0]), "=r"(r[1]), "=r"(r[2]), "=r"(r[3]) : "r"(addr));
}

#define CP16(dst, src) \
  asm volatile("cp.async.cg.shared.global [%0], [%1], 16;" :: "r"(dst), "l"(src))
#define CP_COMMIT() asm volatile("cp.async.commit_group;" ::: "memory")
#define CP_WAIT0() asm volatile("cp.async.wait_group 0;" ::: "memory")
#define CP_WAIT1() asm volatile("cp.async.wait_group 1;" ::: "memory")

// 8 fp32 -> 8 fp16 hi + 8 fp16 lo
__device__ __forceinline__ void cvt8h(float4 a0, float4 a1, uint4& hi, uint4& lo) {
  __half2 h0 = __floats2half2_rn(a0.x, a0.y);
  __half2 h1 = __floats2half2_rn(a0.z, a0.w);
  __half2 h2 = __floats2half2_rn(a1.x, a1.y);
  __half2 h3 = __floats2half2_rn(a1.z, a1.w);
  __half2 l0 = __floats2half2_rn(a0.x - __low2float(h0), a0.y - __high2float(h0));
  __half2 l1 = __floats2half2_rn(a0.z - __low2float(h1), a0.w - __high2float(h1));
  __half2 l2 = __floats2half2_rn(a1.x - __low2float(h2), a1.y - __high2float(h2));
  __half2 l3 = __floats2half2_rn(a1.z - __low2float(h3), a1.w - __high2float(h3));
  hi = make_uint4(*(uint32_t*)&h0, *(uint32_t*)&h1, *(uint32_t*)&h2, *(uint32_t*)&h3);
  lo = make_uint4(*(uint32_t*)&l0, *(uint32_t*)&l1, *(uint32_t*)&l2, *(uint32_t*)&l3);
}
// 8 fp32 -> 8 fp16 (single)
__device__ __forceinline__ uint4 cvt8s(float4 a0, float4 a1) {
  __half2 h0 = __floats2half2_rn(a0.x, a0.y);
  __half2 h1 = __floats2half2_rn(a0.z, a0.w);
  __half2 h2 = __floats2half2_rn(a1.x, a1.y);
  __half2 h3 = __floats2half2_rn(a1.z, a1.w);
  return make_uint4(*(uint32_t*)&h0, *(uint32_t*)&h1, *(uint32_t*)&h2,
                    *(uint32_t*)&h3);
}

// ---------------------------------------------------------------------------
// Kernel 1: QKV projection, fp16 HMMA, y = (xh + xl) * W_fp16.
// Grid (128): one CTA per m-tile, loops y in {q,k,v} internally ->
// exactly one wave, no tail. BK=32, double-buffered, 80B row stride.
// 512 threads, warp grid 4x4, warp tile 32x32.
// ---------------------------------------------------------------------------
#define RSTRIDE 80
#define TILE_B (128 * RSTRIDE)  // 10240
#define NBUF_B (3 * TILE_B)     // Xh, Xl, W

__global__ __launch_bounds__(512) void qkv_hmma(
    const float* __restrict__ x, const float* __restrict__ Wq,
    const float* __restrict__ Wk, const float* __restrict__ Wv) {
  extern __shared__ __align__(1024) char smem[];

  const int tid = threadIdx.x;
  const int lane = tid & 31, wid = tid >> 5;
  const int wm = wid >> 2, wn = wid & 3;
  const int m0 = blockIdx.x * 128;
  const uint32_t sb = smem_u32(smem);

  const int lrow = tid >> 2, lc = tid & 3;
  const float* aSrc = x + (size_t)(m0 + lrow) * DM + lc * 8;
  const uint32_t stoOff = lrow * RSTRIDE + lc * 16;

  const int lane15 = lane & 15;
  const uint32_t aColOff = (lane >> 4) * 16;
  const uint32_t aRowB = (wm * 32 + lane15) * RSTRIDE;
  const uint32_t bRowB = (wn * 32 + ((lane >> 4) << 3) + (lane & 7)) * RSTRIDE;
  const uint32_t bColOff = ((lane >> 3) & 1) * 16;
  const int g = lane >> 2, tig = lane & 3;

  for (int yid = 0; yid < 3; yid++) {
    const float* W = (yid == 0) ? Wq : (yid == 1 ? Wk : Wv);
    const float* bSrc = W + (size_t)lrow * DM + lc * 8;

    float acc[2][4][4];
#pragma unroll
    for (int i = 0; i < 2; i++)
#pragma unroll
      for (int j = 0; j < 4; j++)
#pragma unroll
        for (int r = 0; r < 4; r++) acc[i][j][r] = 0.f;

    float4 pA0, pA1, pB0, pB1;
    pA0 = *(const float4*)(aSrc);
    pA1 = *(const float4*)(aSrc + 4);
    pB0 = *(const float4*)(bSrc);
    pB1 = *(const float4*)(bSrc + 4);
    {
      uint4 hi, lo;
      char* p = smem + stoOff;
      cvt8h(pA0, pA1, hi, lo);
      *(uint4*)(p) = hi;
      *(uint4*)(p + TILE_B) = lo;
      *(uint4*)(p + 2 * TILE_B) = cvt8s(pB0, pB1);
    }
    __syncthreads();

    for (int kt = 0; kt < 32; kt++) {
      if (kt < 31) {
        const float* a = aSrc + (kt + 1) * 32;
        const float* b = bSrc + (kt + 1) * 32;
        pA0 = *(const float4*)(a);
        pA1 = *(const float4*)(a + 4);
        pB0 = *(const float4*)(b);
        pB1 = *(const float4*)(b + 4);
      }
      const uint32_t bufBase = sb + (kt & 1) * NBUF_B;
#pragma unroll
      for (int s = 0; s < 2; s++) {
        uint32_t ah[2][4], al[2][4], b2[2][4];
#pragma unroll
        for (int i = 0; i < 2; i++) {
          uint32_t aa = bufBase + aRowB + i * (16 * RSTRIDE) + s * 32 + aColOff;
          ldm_x4(ah[i], aa);
          ldm_x4(al[i], aa + TILE_B);
        }
#pragma unroll
        for (int j = 0; j < 2; j++) {
          uint32_t ba =
              bufBase + 2 * TILE_B + bRowB + j * (16 * RSTRIDE) + s * 32 + bColOff;
          ldm_x4(b2[j], ba);
        }
#pragma unroll
        for (int i = 0; i < 2; i++)
#pragma unroll
          for (int jj = 0; jj < 4; jj++) {
            const uint32_t* bp = &b2[jj >> 1][(jj & 1) * 2];
            mma_fp16(acc[i][jj], ah[i], bp);
            mma_fp16(acc[i][jj], al[i], bp);
          }
      }
      if (kt < 31) {
        char* p = smem + ((kt + 1) & 1) * NBUF_B + stoOff;
        uint4 hi, lo;
        cvt8h(pA0, pA1, hi, lo);
        *(uint4*)(p) = hi;
        *(uint4*)(p + TILE_B) = lo;
        *(uint4*)(p + 2 * TILE_B) = cvt8s(pB0, pB1);
      }
      __syncthreads();
    }

    // epilogue for this yid (reads regs only; smem safe to reuse next y)
    const float qs = (yid == 0) ? 0.08838834764831845f : 1.0f;
    __half* oh = (yid == 0) ? g_qh : (yid == 1 ? g_kh : g_vh);
#pragma unroll
    for (int i = 0; i < 2; i++) {
      int r0 = m0 + wm * 32 + i * 16 + g;
#pragma unroll
      for (int jj = 0; jj < 4; jj++) {
        int col = wn * 32 + jj * 8 + 2 * tig;
        float v0 = acc[i][jj][0] * qs, v1 = acc[i][jj][1] * qs;
        float v2 = acc[i][jj][2] * qs, v3 = acc[i][jj][3] * qs;
        __half2 h01 = __floats2half2_rn(v0, v1);
        __half2 h23 = __floats2half2_rn(v2, v3);
        *(uint32_t*)&oh[(size_t)r0 * HD + col] = *(uint32_t*)&h01;
        *(uint32_t*)&oh[(size_t)(r0 + 8) * HD + col] = *(uint32_t*)&h23;
        if (yid == 0) {
          __half2 l01 =
              __floats2half2_rn(v0 - __low2float(h01), v1 - __high2float(h01));
          __half2 l23 =
              __floats2half2_rn(v2 - __low2float(h23), v3 - __high2float(h23));
          *(uint32_t*)&g_ql[(size_t)r0 * HD + col] = *(uint32_t*)&l01;
          *(uint32_t*)&g_ql[(size_t)(r0 + 8) * HD + col] = *(uint32_t*)&l23;
        }
      }
    }
  }
}

// ---------------------------------------------------------------------------
// Kernel 2: causal flash attention, fp16 HMMA. S = (Qh+Ql)K (2 MMAs),
// O += P_fp16 V (1 MMA; P in [0,1], 2^-12 quantization). 512 thr,
// cp.async double-buffered KV, paired q-tiles: 33 iters/CTA, grid (16,8).
// ---------------------------------------------------------------------------
#define QSTR 272
#define PSTR 144
#define KVB_K 17408
#define KVSTG 34816
#define OFF_KV 34816
#define OFF_P (OFF_KV + 2 * KVSTG)   // 104448
#define OFF_MS (OFF_P + 9216)        // 113664
#define ATT_SMEM (OFF_MS + 1024)     // 114688

__global__ __launch_bounds__(512) void attn_mma(float* __restrict__ out) {
  extern __shared__ __align__(16) char smA[];
  const uint32_t sb = smem_u32(smA);
  float* msm = (float*)(smA + OFF_MS);

  const int tid = threadIdx.x, lane = tid & 31, wid = tid >> 5;
  const int wm = wid & 3, wn = wid >> 2;
  const int g = lane >> 2, tig = lane & 3;
  const int b = blockIdx.y;

  const int aRow = lane & 15;
  const int aCol = (lane >> 4) * 16;
  const int bRow = ((lane >> 4) << 3) + (lane & 7);
  const int bCol = ((lane >> 3) & 1) * 16;
  const int vRow = (lane & 7) + (((lane >> 3) & 1) << 3);
  const int vCol = (lane >> 4) * 8;
  const int rA = 16 * wm + g;

  const int ldRow = tid >> 3, ldC = tid & 7;
  const uint32_t ldDst = ldRow * QSTR + ldC * 16;
  const size_t ldSrc = (size_t)ldRow * HD + ldC * 8;

  for (int phse = 0; phse < 2; phse++) {
    const int qt = phse ? (31 - blockIdx.x) : blockIdx.x;
    const size_t qoff = ((size_t)b * TSEQ + (size_t)qt * 64) * HD;
    __syncthreads();
    {
      const uint4* qhp = (const uint4*)(g_qh + qoff);
      const uint4* qlp = (const uint4*)(g_ql + qoff);
#pragma unroll
      for (int it = 0; it < 2; it++) {
        int idx = tid + it * 512;
        uint32_t d = (idx >> 4) * QSTR + (idx & 15) * 16;
        *(uint4*)(smA + d) = qhp[idx];
        *(uint4*)(smA + KVB_K + d) = qlp[idx];
      }
    }
    {
      const size_t koff = (size_t)b * TSEQ * HD;
      const uint32_t d0 = sb + OFF_KV + ldDst;
      CP16(d0, g_kh + koff + ldSrc);
      CP16(d0 + 128, g_kh + koff + ldSrc + 64);
      CP16(d0 + KVB_K, g_vh + koff + ldSrc);
      CP16(d0 + KVB_K + 128, g_vh + koff + ldSrc + 64);
      CP_COMMIT();
    }

    float O[4][4];
#pragma unroll
    for (int nt = 0; nt < 4; nt++)
#pragma unroll
      for (int r = 0; r < 4; r++) O[nt][r] = 0.f;
    float m_r[2] = {-1e30f, -1e30f}, l_r[2] = {0.f, 0.f};

    for (int kb = 0; kb <= qt; kb++) {
      const uint32_t kvb = sb + OFF_KV + (kb & 1) * KVSTG;
      if (kb < qt) {
        const size_t koff = ((size_t)b * TSEQ + (size_t)(kb + 1) * 64) * HD;
        const uint32_t ob = sb + OFF_KV + ((kb + 1) & 1) * KVSTG + ldDst;
        CP16(ob, g_kh + koff + ldSrc);
        CP16(ob + 128, g_kh + koff + ldSrc + 64);
        CP16(ob + KVB_K, g_vh + koff + ldSrc);
        CP16(ob + KVB_K + 128, g_vh + koff + ldSrc + 64);
        CP_COMMIT();
        CP_WAIT1();
      } else {
        CP_WAIT0();
      }
      __syncthreads();

      float sfr[2][4];
#pragma unroll
      for (int nt = 0; nt < 2; nt++)
#pragma unroll
        for (int r = 0; r < 4; r++) sfr[nt][r] = 0.f;
#pragma unroll
      for (int c = 0; c < 8; c++) {
        uint32_t qh4[4], ql4[4], kh4[4];
        uint32_t qa = sb + (16 * wm + aRow) * QSTR + c * 32 + aCol;
        ldm_x4(qh4, qa);
        ldm_x4(ql4, qa + KVB_K);
        ldm_x4(kh4, kvb + (16 * wn + bRow) * QSTR + c * 32 + bCol);
#pragma unroll
        for (int h = 0; h < 2; h++) {
          mma_fp16(sfr[h], qh4, &kh4[2 * h]);
          mma_fp16(sfr[h], ql4, &kh4[2 * h]);
        }
      }

      if (kb == qt) {
#pragma unroll
        for (int nt = 0; nt < 2; nt++) {
          int colRel = 16 * wn + 8 * nt + 2 * tig;
          if (colRel > rA) sfr[nt][0] = -1e30f;
          if (colRel + 1 > rA) sfr[nt][1] = -1e30f;
          if (colRel > rA + 8) sfr[nt][2] = -1e30f;
          if (colRel + 1 > rA + 8) sfr[nt][3] = -1e30f;
        }
      }

      float mxA = fmaxf(fmaxf(sfr[0][0], sfr[0][1]), fmaxf(sfr[1][0], sfr[1][1]));
      float mxB = fmaxf(fmaxf(sfr[0][2], sfr[0][3]), fmaxf(sfr[1][2], sfr[1][3]));
#pragma unroll
      for (int o = 1; o <= 2; o <<= 1) {
        mxA = fmaxf(mxA, __shfl_xor_sync(0xffffffffu, mxA, o));
        mxB = fmaxf(mxB, __shfl_xor_sync(0xffffffffu, mxB, o));
      }
      if (tig == 0) {
        msm[rA * 4 + wn] = mxA;
        msm[(rA + 8) * 4 + wn] = mxB;
      }
      __syncthreads();
      float nmA = fmaxf(m_r[0],
                        fmaxf(fmaxf(msm[rA * 4 + 0], msm[rA * 4 + 1]),
                              fmaxf(msm[rA * 4 + 2], msm[rA * 4 + 3])));
      float nmB = fmaxf(m_r[1],
                        fmaxf(fmaxf(msm[(rA + 8) * 4 + 0], msm[(rA + 8) * 4 + 1]),
                              fmaxf(msm[(rA + 8) * 4 + 2], msm[(rA + 8) * 4 + 3])));
      float corrA = __expf(m_r[0] - nmA);
      float corrB = __expf(m_r[1] - nmB);
      m_r[0] = nmA;
      m_r[1] = nmB;

      float sumA = 0.f, sumB = 0.f;
#pragma unroll
      for (int nt = 0; nt < 2; nt++) {
        float pa0 = __expf(sfr[nt][0] - nmA), pa1 = __expf(sfr[nt][1] - nmA);
        float pb0 = __expf(sfr[nt][2] - nmB), pb1 = __expf(sfr[nt][3] - nmB);
        sumA += pa0 + pa1;
        sumB += pb0 + pb1;
        int colb = (16 * wn + 8 * nt + 2 * tig) * 2;
        __half2 ha = __floats2half2_rn(pa0, pa1);
        __half2 hb = __floats2half2_rn(pb0, pb1);
        *(uint32_t*)(smA + OFF_P + rA * PSTR + colb) = *(uint32_t*)&ha;
        *(uint32_t*)(smA + OFF_P + (rA + 8) * PSTR + colb) = *(uint32_t*)&hb;
      }
#pragma unroll
      for (int o = 1; o <= 2; o <<= 1) {
        sumA += __shfl_xor_sync(0xffffffffu, sumA, o);
        sumB += __shfl_xor_sync(0xffffffffu, sumB, o);
      }
      l_r[0] = l_r[0] * corrA + sumA;
      l_r[1] = l_r[1] * corrB + sumB;
#pragma unroll
      for (int nt = 0; nt < 4; nt++) {
        O[nt][0] *= corrA;
        O[nt][1] *= corrA;
        O[nt][2] *= corrB;
        O[nt][3] *= corrB;
      }
      __syncthreads();

#pragma unroll
      for (int ck = 0; ck < 4; ck++) {
        uint32_t pfh[4];
        uint32_t ad = sb + OFF_P + (16 * wm + aRow) * PSTR + ck * 32 + aCol;
        ldm_x4(pfh, ad);
#pragma unroll
        for (int pv = 0; pv < 2; pv++) {
          uint32_t vh4[4];
          uint32_t vd = kvb + KVB_K + (16 * ck + vRow) * QSTR +
                        (32 * wn + 16 * pv + vCol) * 2;
          ldm_x4_t(vh4, vd);
#pragma unroll
          for (int h = 0; h < 2; h++) {
            int nt = 2 * pv + h;
            mma_fp16(O[nt], pfh, &vh4[2 * h]);
          }
        }
      }
      __syncthreads();
    }

    if (tig == 0) {
      msm[rA * 4 + wn] = l_r[0];
      msm[(rA + 8) * 4 + wn] = l_r[1];
    }
    __syncthreads();
    float liA = 1.f / (msm[rA * 4 + 0] + msm[rA * 4 + 1] + msm[rA * 4 + 2] +
                       msm[rA * 4 + 3]);
    float liB = 1.f / (msm[(rA + 8) * 4 + 0] + msm[(rA + 8) * 4 + 1] +
                       msm[(rA + 8) * 4 + 2] + msm[(rA + 8) * 4 + 3]);
    const size_t tA = (size_t)b * TSEQ + qt * 64 + rA;
#pragma unroll
    for (int nt = 0; nt < 4; nt++) {
      int col = 32 * wn + 8 * nt + 2 * tig;
      *(float2*)&out[tA * HD + col] = make_float2(O[nt][0] * liA, O[nt][1] * liA);
      *(float2*)&out[(tA + 8) * HD + col] =
          make_float2(O[nt][2] * liB, O[nt][3] * liB);
    }
  }
}

extern "C" void kernel_launch(void* const* d_in, const int* in_sizes, int n_in,
                              void* d_out, int out_size) {
  (void)in_sizes; (void)n_in; (void)out_size;
  const float* x  = (const float*)d_in[0];
  const float* Wq = (const float*)d_in[1];
  const float* Wk = (const float*)d_in[2];
  const float* Wv = (const float*)d_in[3];
  float* out = (float*)d_out;

  const int SMEMQ = 2 * NBUF_B;  // 61440 B
  cudaFuncSetAttribute(qkv_hmma, cudaFuncAttributeMaxDynamicSharedMemorySize,
                       SMEMQ);
  qkv_hmma<<<128, 512, SMEMQ>>>(x, Wq, Wk, Wv);

  cudaFuncSetAttribute(attn_mma, cudaFuncAttributeMaxDynamicSharedMemorySize,
                       ATT_SMEM);
  dim3 g2(16, 8);
  attn_mma<<<g2, 512, ATT_SMEM>>>(out);
}

// round 10
// speedup vs baseline: 5.0598x; 1.0988x over previous
#include <cuda_runtime.h>
#include <cuda_fp16.h>
#include <cstdint>

#define TSEQ 2048
#define BATCH 8
#define DM 1024
#define HD 128
#define MTOT (BATCH * TSEQ)

// fp16 scratch: Q split-2 (hi+lo), K/V single. Q pre-scaled by 1/sqrt(HD).
__device__ __align__(16) __half g_qh[MTOT * HD];
__device__ __align__(16) __half g_ql[MTOT * HD];
__device__ __align__(16) __half g_kh[MTOT * HD];
__device__ __align__(16) __half g_vh[MTOT * HD];

__device__ __forceinline__ uint32_t smem_u32(const void* p) {
  return (uint32_t)__cvta_generic_to_shared(p);
}

__device__ __forceinline__ void mma_fp16(float* d, const uint32_t* a,
                                         const uint32_t* b) {
  asm volatile(
      "mma.sync.aligned.m16n8k16.row.col.f32.f16.f16.f32 "
      "{%0,%1,%2,%3}, {%4,%5,%6,%7}, {%8,%9}, {%0,%1,%2,%3};\n"
      : "+f"(d[0]), "+f"(d[1]), "+f"(d[2]), "+f"(d[3])
      : "r"(a[0]), "r"(a[1]), "r"(a[2]), "r"(a[3]), "r"(b[0]), "r"(b[1]));
}

__device__ __forceinline__ void ldm_x4(uint32_t* r, uint32_t addr) {
  asm volatile(
      "ldmatrix.sync.aligned.m8n8.x4.shared.b16 {%0,%1,%2,%3}, [%4];"
      : "=r"(r[0]), "=r"(r[1]), "=r"(r[2]), "=r"(r[3]) : "r"(addr));
}
__device__ __forceinline__ void ldm_x4_t(uint32_t* r, uint32_t addr) {
  asm volatile(
      "ldmatrix.sync.aligned.m8n8.x4.trans.shared.b16 {%0,%1,%2,%3}, [%4];"
      : "=r"(r[0]), "=r"(r[1]), "=r"(r[2]), "=r"(r[3]) : "r"(addr));
}

#define CP16(dst, src) \
  asm volatile("cp.async.cg.shared.global [%0], [%1], 16;" :: "r"(dst), "l"(src))
#define CP_COMMIT() asm volatile("cp.async.commit_group;" ::: "memory")
#define CP_WAIT0() asm volatile("cp.async.wait_group 0;" ::: "memory")
#define CP_WAIT1() asm volatile("cp.async.wait_group 1;" ::: "memory")

// 8 fp32 -> 8 fp16 hi + 8 fp16 lo
__device__ __forceinline__ void cvt8h(float4 a0, float4 a1, uint4& hi, uint4& lo) {
  __half2 h0 = __floats2half2_rn(a0.x, a0.y);
  __half2 h1 = __floats2half2_rn(a0.z, a0.w);
  __half2 h2 = __floats2half2_rn(a1.x, a1.y);
  __half2 h3 = __floats2half2_rn(a1.z, a1.w);
  __half2 l0 = __floats2half2_rn(a0.x - __low2float(h0), a0.y - __high2float(h0));
  __half2 l1 = __floats2half2_rn(a0.z - __low2float(h1), a0.w - __high2float(h1));
  __half2 l2 = __floats2half2_rn(a1.x - __low2float(h2), a1.y - __high2float(h2));
  __half2 l3 = __floats2half2_rn(a1.z - __low2float(h3), a1.w - __high2float(h3));
  hi = make_uint4(*(uint32_t*)&h0, *(uint32_t*)&h1, *(uint32_t*)&h2, *(uint32_t*)&h3);
  lo = make_uint4(*(uint32_t*)&l0, *(uint32_t*)&l1, *(uint32_t*)&l2, *(uint32_t*)&l3);
}
// 8 fp32 -> 8 fp16 (single)
__device__ __forceinline__ uint4 cvt8s(float4 a0, float4 a1) {
  __half2 h0 = __floats2half2_rn(a0.x, a0.y);
  __half2 h1 = __floats2half2_rn(a0.z, a0.w);
  __half2 h2 = __floats2half2_rn(a1.x, a1.y);
  __half2 h3 = __floats2half2_rn(a1.z, a1.w);
  return make_uint4(*(uint32_t*)&h0, *(uint32_t*)&h1, *(uint32_t*)&h2,
                    *(uint32_t*)&h3);
}

// ---------------------------------------------------------------------------
// Kernel 1: QKV projection, fp16 HMMA. Grid (128,3), 2 CTAs/SM.
//   q (y=0): (xh + xl) * W   (2 MMAs, split-2 x — q feeds attn's S-split)
//   k,v    : xh * W          (1 MMA, x-lo dropped; extra ~2.4e-4 error)
// BK=32, double-buffered smem, 80B row stride. 512 thr, warp grid 4x4.
// ---------------------------------------------------------------------------
#define RSTRIDE 80
#define TILE_B (128 * RSTRIDE)  // 10240
#define NBUF_B (3 * TILE_B)     // Xh, Xl, W

__global__ __launch_bounds__(512) void qkv_hmma(
    const float* __restrict__ x, const float* __restrict__ Wq,
    const float* __restrict__ Wk, const float* __restrict__ Wv) {
  extern __shared__ __align__(1024) char smem[];
  const int yid = blockIdx.y;
  const float* W = (yid == 0) ? Wq : (yid == 1 ? Wk : Wv);
  const bool useLo = (yid == 0);

  const int tid = threadIdx.x;
  const int lane = tid & 31, wid = tid >> 5;
  const int wm = wid >> 2, wn = wid & 3;
  const int m0 = blockIdx.x * 128;
  const uint32_t sb = smem_u32(smem);

  const int lrow = tid >> 2, lc = tid & 3;
  const float* aSrc = x + (size_t)(m0 + lrow) * DM + lc * 8;
  const float* bSrc = W + (size_t)lrow * DM + lc * 8;
  const uint32_t stoOff = lrow * RSTRIDE + lc * 16;

  const int lane15 = lane & 15;
  const uint32_t aColOff = (lane >> 4) * 16;
  const uint32_t aRowB = (wm * 32 + lane15) * RSTRIDE;
  const uint32_t bRowB = (wn * 32 + ((lane >> 4) << 3) + (lane & 7)) * RSTRIDE;
  const uint32_t bColOff = ((lane >> 3) & 1) * 16;

  float acc[2][4][4];
#pragma unroll
  for (int i = 0; i < 2; i++)
#pragma unroll
    for (int j = 0; j < 4; j++)
#pragma unroll
      for (int r = 0; r < 4; r++) acc[i][j][r] = 0.f;

  float4 pA0, pA1, pB0, pB1;
  pA0 = *(const float4*)(aSrc);
  pA1 = *(const float4*)(aSrc + 4);
  pB0 = *(const float4*)(bSrc);
  pB1 = *(const float4*)(bSrc + 4);
  {
    char* p = smem + stoOff;
    if (useLo) {
      uint4 hi, lo;
      cvt8h(pA0, pA1, hi, lo);
      *(uint4*)(p) = hi;
      *(uint4*)(p + TILE_B) = lo;
    } else {
      *(uint4*)(p) = cvt8s(pA0, pA1);
    }
    *(uint4*)(p + 2 * TILE_B) = cvt8s(pB0, pB1);
  }
  __syncthreads();

  for (int kt = 0; kt < 32; kt++) {
    if (kt < 31) {
      const float* a = aSrc + (kt + 1) * 32;
      const float* b = bSrc + (kt + 1) * 32;
      pA0 = *(const float4*)(a);
      pA1 = *(const float4*)(a + 4);
      pB0 = *(const float4*)(b);
      pB1 = *(const float4*)(b + 4);
    }
    const uint32_t bufBase = sb + (kt & 1) * NBUF_B;
#pragma unroll
    for (int s = 0; s < 2; s++) {
      uint32_t ah[2][4], al[2][4], b2[2][4];
#pragma unroll
      for (int i = 0; i < 2; i++) {
        uint32_t aa = bufBase + aRowB + i * (16 * RSTRIDE) + s * 32 + aColOff;
        ldm_x4(ah[i], aa);
        if (useLo) ldm_x4(al[i], aa + TILE_B);
      }
#pragma unroll
      for (int j = 0; j < 2; j++) {
        uint32_t ba =
            bufBase + 2 * TILE_B + bRowB + j * (16 * RSTRIDE) + s * 32 + bColOff;
        ldm_x4(b2[j], ba);
      }
#pragma unroll
      for (int i = 0; i < 2; i++)
#pragma unroll
        for (int jj = 0; jj < 4; jj++) {
          const uint32_t* bp = &b2[jj >> 1][(jj & 1) * 2];
          mma_fp16(acc[i][jj], ah[i], bp);
          if (useLo) mma_fp16(acc[i][jj], al[i], bp);
        }
    }
    if (kt < 31) {
      char* p = smem + ((kt + 1) & 1) * NBUF_B + stoOff;
      if (useLo) {
        uint4 hi, lo;
        cvt8h(pA0, pA1, hi, lo);
        *(uint4*)(p) = hi;
        *(uint4*)(p + TILE_B) = lo;
      } else {
        *(uint4*)(p) = cvt8s(pA0, pA1);
      }
      *(uint4*)(p + 2 * TILE_B) = cvt8s(pB0, pB1);
    }
    __syncthreads();
  }

  const int g = lane >> 2, tig = lane & 3;
  const float qs = (yid == 0) ? 0.08838834764831845f : 1.0f;
  __half* oh = (yid == 0) ? g_qh : (yid == 1 ? g_kh : g_vh);
#pragma unroll
  for (int i = 0; i < 2; i++) {
    int r0 = m0 + wm * 32 + i * 16 + g;
#pragma unroll
    for (int jj = 0; jj < 4; jj++) {
      int col = wn * 32 + jj * 8 + 2 * tig;
      float v0 = acc[i][jj][0] * qs, v1 = acc[i][jj][1] * qs;
      float v2 = acc[i][jj][2] * qs, v3 = acc[i][jj][3] * qs;
      __half2 h01 = __floats2half2_rn(v0, v1);
      __half2 h23 = __floats2half2_rn(v2, v3);
      *(uint32_t*)&oh[(size_t)r0 * HD + col] = *(uint32_t*)&h01;
      *(uint32_t*)&oh[(size_t)(r0 + 8) * HD + col] = *(uint32_t*)&h23;
      if (yid == 0) {
        __half2 l01 =
            __floats2half2_rn(v0 - __low2float(h01), v1 - __high2float(h01));
        __half2 l23 =
            __floats2half2_rn(v2 - __low2float(h23), v3 - __high2float(h23));
        *(uint32_t*)&g_ql[(size_t)r0 * HD + col] = *(uint32_t*)&l01;
        *(uint32_t*)&g_ql[(size_t)(r0 + 8) * HD + col] = *(uint32_t*)&l23;
      }
    }
  }
}

// ---------------------------------------------------------------------------
// Kernel 2: causal flash attention (unchanged, known-good 76.2us).
// fp16 HMMA: S = (Qh+Ql)K (2 MMAs), O += P_fp16 V (1 MMA). 512 thr,
// cp.async double-buffered KV, paired q-tiles: 33 iters/CTA, grid (16,8).
// ---------------------------------------------------------------------------
#define QSTR 272
#define PSTR 144
#define KVB_K 17408
#define KVSTG 34816
#define OFF_KV 34816
#define OFF_P (OFF_KV + 2 * KVSTG)   // 104448
#define OFF_MS (OFF_P + 9216)        // 113664
#define ATT_SMEM (OFF_MS + 1024)     // 114688

__global__ __launch_bounds__(512) void attn_mma(float* __restrict__ out) {
  extern __shared__ __align__(16) char smA[];
  const uint32_t sb = smem_u32(smA);
  float* msm = (float*)(smA + OFF_MS);

  const int tid = threadIdx.x, lane = tid & 31, wid = tid >> 5;
  const int wm = wid & 3, wn = wid >> 2;
  const int g = lane >> 2, tig = lane & 3;
  const int b = blockIdx.y;

  const int aRow = lane & 15;
  const int aCol = (lane >> 4) * 16;
  const int bRow = ((lane >> 4) << 3) + (lane & 7);
  const int bCol = ((lane >> 3) & 1) * 16;
  const int vRow = (lane & 7) + (((lane >> 3) & 1) << 3);
  const int vCol = (lane >> 4) * 8;
  const int rA = 16 * wm + g;

  const int ldRow = tid >> 3, ldC = tid & 7;
  const uint32_t ldDst = ldRow * QSTR + ldC * 16;
  const size_t ldSrc = (size_t)ldRow * HD + ldC * 8;

  for (int phse = 0; phse < 2; phse++) {
    const int qt = phse ? (31 - blockIdx.x) : blockIdx.x;
    const size_t qoff = ((size_t)b * TSEQ + (size_t)qt * 64) * HD;
    __syncthreads();
    {
      const uint4* qhp = (const uint4*)(g_qh + qoff);
      const uint4* qlp = (const uint4*)(g_ql + qoff);
#pragma unroll
      for (int it = 0; it < 2; it++) {
        int idx = tid + it * 512;
        uint32_t d = (idx >> 4) * QSTR + (idx & 15) * 16;
        *(uint4*)(smA + d) = qhp[idx];
        *(uint4*)(smA + KVB_K + d) = qlp[idx];
      }
    }
    {
      const size_t koff = (size_t)b * TSEQ * HD;
      const uint32_t d0 = sb + OFF_KV + ldDst;
      CP16(d0, g_kh + koff + ldSrc);
      CP16(d0 + 128, g_kh + koff + ldSrc + 64);
      CP16(d0 + KVB_K, g_vh + koff + ldSrc);
      CP16(d0 + KVB_K + 128, g_vh + koff + ldSrc + 64);
      CP_COMMIT();
    }

    float O[4][4];
#pragma unroll
    for (int nt = 0; nt < 4; nt++)
#pragma unroll
      for (int r = 0; r < 4; r++) O[nt][r] = 0.f;
    float m_r[2] = {-1e30f, -1e30f}, l_r[2] = {0.f, 0.f};

    for (int kb = 0; kb <= qt; kb++) {
      const uint32_t kvb = sb + OFF_KV + (kb & 1) * KVSTG;
      if (kb < qt) {
        const size_t koff = ((size_t)b * TSEQ + (size_t)(kb + 1) * 64) * HD;
        const uint32_t ob = sb + OFF_KV + ((kb + 1) & 1) * KVSTG + ldDst;
        CP16(ob, g_kh + koff + ldSrc);
        CP16(ob + 128, g_kh + koff + ldSrc + 64);
        CP16(ob + KVB_K, g_vh + koff + ldSrc);
        CP16(ob + KVB_K + 128, g_vh + koff + ldSrc + 64);
        CP_COMMIT();
        CP_WAIT1();
      } else {
        CP_WAIT0();
      }
      __syncthreads();

      float sfr[2][4];
#pragma unroll
      for (int nt = 0; nt < 2; nt++)
#pragma unroll
        for (int r = 0; r < 4; r++) sfr[nt][r] = 0.f;
#pragma unroll
      for (int c = 0; c < 8; c++) {
        uint32_t qh4[4], ql4[4], kh4[4];
        uint32_t qa = sb + (16 * wm + aRow) * QSTR + c * 32 + aCol;
        ldm_x4(qh4, qa);
        ldm_x4(ql4, qa + KVB_K);
        ldm_x4(kh4, kvb + (16 * wn + bRow) * QSTR + c * 32 + bCol);
#pragma unroll
        for (int h = 0; h < 2; h++) {
          mma_fp16(sfr[h], qh4, &kh4[2 * h]);
          mma_fp16(sfr[h], ql4, &kh4[2 * h]);
        }
      }

      if (kb == qt) {
#pragma unroll
        for (int nt = 0; nt < 2; nt++) {
          int colRel = 16 * wn + 8 * nt + 2 * tig;
          if (colRel > rA) sfr[nt][0] = -1e30f;
          if (colRel + 1 > rA) sfr[nt][1] = -1e30f;
          if (colRel > rA + 8) sfr[nt][2] = -1e30f;
          if (colRel + 1 > rA + 8) sfr[nt][3] = -1e30f;
        }
      }

      float mxA = fmaxf(fmaxf(sfr[0][0], sfr[0][1]), fmaxf(sfr[1][0], sfr[1][1]));
      float mxB = fmaxf(fmaxf(sfr[0][2], sfr[0][3]), fmaxf(sfr[1][2], sfr[1][3]));
#pragma unroll
      for (int o = 1; o <= 2; o <<= 1) {
        mxA = fmaxf(mxA, __shfl_xor_sync(0xffffffffu, mxA, o));
        mxB = fmaxf(mxB, __shfl_xor_sync(0xffffffffu, mxB, o));
      }
      if (tig == 0) {
        msm[rA * 4 + wn] = mxA;
        msm[(rA + 8) * 4 + wn] = mxB;
      }
      __syncthreads();
      float nmA = fmaxf(m_r[0],
                        fmaxf(fmaxf(msm[rA * 4 + 0], msm[rA * 4 + 1]),
                              fmaxf(msm[rA * 4 + 2], msm[rA * 4 + 3])));
      float nmB = fmaxf(m_r[1],
                        fmaxf(fmaxf(msm[(rA + 8) * 4 + 0], msm[(rA + 8) * 4 + 1]),
                              fmaxf(msm[(rA + 8) * 4 + 2], msm[(rA + 8) * 4 + 3])));
      float corrA = __expf(m_r[0] - nmA);
      float corrB = __expf(m_r[1] - nmB);
      m_r[0] = nmA;
      m_r[1] = nmB;

      float sumA = 0.f, sumB = 0.f;
#pragma unroll
      for (int nt = 0; nt < 2; nt++) {
        float pa0 = __expf(sfr[nt][0] - nmA), pa1 = __expf(sfr[nt][1] - nmA);
        float pb0 = __expf(sfr[nt][2] - nmB), pb1 = __expf(sfr[nt][3] - nmB);
        sumA += pa0 + pa1;
        sumB += pb0 + pb1;
        int colb = (16 * wn + 8 * nt + 2 * tig) * 2;
        __half2 ha = __floats2half2_rn(pa0, pa1);
        __half2 hb = __floats2half2_rn(pb0, pb1);
        *(uint32_t*)(smA + OFF_P + rA * PSTR + colb) = *(uint32_t*)&ha;
        *(uint32_t*)(smA + OFF_P + (rA + 8) * PSTR + colb) = *(uint32_t*)&hb;
      }
#pragma unroll
      for (int o = 1; o <= 2; o <<= 1) {
        sumA += __shfl_xor_sync(0xffffffffu, sumA, o);
        sumB += __shfl_xor_sync(0xffffffffu, sumB, o);
      }
      l_r[0] = l_r[0] * corrA + sumA;
      l_r[1] = l_r[1] * corrB + sumB;
#pragma unroll
      for (int nt = 0; nt < 4; nt++) {
        O[nt][0] *= corrA;
        O[nt][1] *= corrA;
        O[nt][2] *= corrB;
        O[nt][3] *= corrB;
      }
      __syncthreads();

#pragma unroll
      for (int ck = 0; ck < 4; ck++) {
        uint32_t pfh[4];
        uint32_t ad = sb + OFF_P + (16 * wm + aRow) * PSTR + ck * 32 + aCol;
        ldm_x4(pfh, ad);
#pragma unroll
        for (int pv = 0; pv < 2; pv++) {
          uint32_t vh4[4];
          uint32_t vd = kvb + KVB_K + (16 * ck + vRow) * QSTR +
                        (32 * wn + 16 * pv + vCol) * 2;
          ldm_x4_t(vh4, vd);
#pragma unroll
          for (int h = 0; h < 2; h++) {
            int nt = 2 * pv + h;
            mma_fp16(O[nt], pfh, &vh4[2 * h]);
          }
        }
      }
      __syncthreads();
    }

    if (tig == 0) {
      msm[rA * 4 + wn] = l_r[0];
      msm[(rA + 8) * 4 + wn] = l_r[1];
    }
    __syncthreads();
    float liA = 1.f / (msm[rA * 4 + 0] + msm[rA * 4 + 1] + msm[rA * 4 + 2] +
                       msm[rA * 4 + 3]);
    float liB = 1.f / (msm[(rA + 8) * 4 + 0] + msm[(rA + 8) * 4 + 1] +
                       msm[(rA + 8) * 4 + 2] + msm[(rA + 8) * 4 + 3]);
    const size_t tA = (size_t)b * TSEQ + qt * 64 + rA;
#pragma unroll
    for (int nt = 0; nt < 4; nt++) {
      int col = 32 * wn + 8 * nt + 2 * tig;
      *(float2*)&out[tA * HD + col] = make_float2(O[nt][0] * liA, O[nt][1] * liA);
      *(float2*)&out[(tA + 8) * HD + col] =
          make_float2(O[nt][2] * liB, O[nt][3] * liB);
    }
  }
}

extern "C" void kernel_launch(void* const* d_in, const int* in_sizes, int n_in,
                              void* d_out, int out_size) {
  (void)in_sizes; (void)n_in; (void)out_size;
  const float* x  = (const float*)d_in[0];
  const float* Wq = (const float*)d_in[1];
  const float* Wk = (const float*)d_in[2];
  const float* Wv = (const float*)d_in[3];
  float* out = (float*)d_out;

  const int SMEMQ = 2 * NBUF_B;  // 61440 B
  cudaFuncSetAttribute(qkv_hmma, cudaFuncAttributeMaxDynamicSharedMemorySize,
                       SMEMQ);
  dim3 g1(128, 3);
  qkv_hmma<<<g1, 512, SMEMQ>>>(x, Wq, Wk, Wv);

  cudaFuncSetAttribute(attn_mma, cudaFuncAttributeMaxDynamicSharedMemorySize,
                       ATT_SMEM);
  dim3 g2(16, 8);
  attn_mma<<<g2, 512, ATT_SMEM>>>(out);
}